// round 10
// baseline (speedup 1.0000x reference)
#include <cuda_runtime.h>
#include <cuda_fp16.h>
#include <cstdint>
#include <math.h>

// Problem dims (fixed by reference)
#define BATCH 2
#define SEQ 2048
#define DMODEL 2048
#define NH 16
#define NKV 4
#define HD 128
#define MTOK (BATCH * SEQ)          // 4096 tokens
#define KVDIM (NKV * HD)            // 512
#define QKVN (DMODEL + 2 * KVDIM)   // 3072

// ---------------------------------------------------------------------------
// Scratch (device globals; runtime allocation is forbidden)
// ---------------------------------------------------------------------------
__device__ float g_q[MTOK * NH * HD];
__device__ float g_k[MTOK * KVDIM];

__device__ __half g_xh[MTOK * DMODEL];
__device__ __half g_aoh[MTOK * DMODEL];
__device__ __half g_qh[MTOK * NH * HD];
__device__ __half g_kh[MTOK * KVDIM];
__device__ __half g_kl[MTOK * KVDIM];
__device__ __half g_vh[MTOK * KVDIM];
__device__ __half g_vl[MTOK * KVDIM];
// combined QKV weights [3072, 2048] (rows: wq 0-2047, wk 2048-2559, wv 2560-3071)
__device__ __half g_wqkv_h[QKVN * DMODEL];
__device__ __half g_wqkv_l[QKVN * DMODEL];
__device__ __half g_wo_h[DMODEL * DMODEL];
__device__ __half g_wo_l[DMODEL * DMODEL];

#define LO_SCALE 1024.0f
#define INV_LO_SCALE 0.0009765625f
#define HSC2 0x14001400u                     // fp16x2 constant 2^-10

// ---------------------------------------------------------------------------
// helpers
// ---------------------------------------------------------------------------
__device__ __forceinline__ uint32_t smem_u32(const void* p) {
  uint32_t a;
  asm("{ .reg .u64 t; cvta.to.shared.u64 t, %1; cvt.u32.u64 %0, t; }"
      : "=r"(a) : "l"(p));
  return a;
}
__device__ __forceinline__ void cpa16(uint32_t s, const void* g) {
  asm volatile("cp.async.cg.shared.global [%0], [%1], 16;"
               :: "r"(s), "l"(g) : "memory");
}
__device__ __forceinline__ void cpa_commit() {
  asm volatile("cp.async.commit_group;" ::: "memory");
}
__device__ __forceinline__ void cpa_wait0() {
  asm volatile("cp.async.wait_group 0;" ::: "memory");
}
__device__ __forceinline__ void cpa_wait1() {
  asm volatile("cp.async.wait_group 1;" ::: "memory");
}
__device__ __forceinline__ void ldsm_x4(uint32_t addr, uint32_t* r) {
  asm volatile("ldmatrix.sync.aligned.m8n8.x4.shared.b16 {%0,%1,%2,%3}, [%4];"
               : "=r"(r[0]), "=r"(r[1]), "=r"(r[2]), "=r"(r[3]) : "r"(addr));
}
__device__ __forceinline__ void ldsm_x4_t(uint32_t addr, uint32_t* r) {
  asm volatile("ldmatrix.sync.aligned.m8n8.x4.trans.shared.b16 {%0,%1,%2,%3}, [%4];"
               : "=r"(r[0]), "=r"(r[1]), "=r"(r[2]), "=r"(r[3]) : "r"(addr));
}
__device__ __forceinline__ void mma_f16(float* d, const uint32_t* a,
                                        const uint32_t* b) {
  asm volatile(
      "mma.sync.aligned.m16n8k16.row.col.f32.f16.f16.f32 "
      "{%0,%1,%2,%3}, {%4,%5,%6,%7}, {%8,%9}, {%0,%1,%2,%3};"
      : "+f"(d[0]), "+f"(d[1]), "+f"(d[2]), "+f"(d[3])
      : "r"(a[0]), "r"(a[1]), "r"(a[2]), "r"(a[3]), "r"(b[0]), "r"(b[1]));
}
__device__ __forceinline__ uint32_t pack_f16(float a, float b) {
  uint32_t r;
  asm("cvt.rn.f16x2.f32 %0, %1, %2;" : "=r"(r) : "f"(b), "f"(a));
  return r;
}
__device__ __forceinline__ float f16_round(float f) {
  return __half2float(__float2half(f));
}
__device__ __forceinline__ uint32_t hscale(uint32_t x) {
  uint32_t r;
  asm("mul.f16x2 %0, %1, %2;" : "=r"(r) : "r"(x), "r"(HSC2));
  return r;
}

// ---------------------------------------------------------------------------
// Conversion kernels
// ---------------------------------------------------------------------------
__global__ void round_kernel(const float* __restrict__ src,
                             __half* __restrict__ dst, int n) {
  int i = blockIdx.x * blockDim.x + threadIdx.x;
  if (i >= n) return;
  dst[i] = __float2half(src[i]);
}

__global__ void transpose_split_kernel(const float* __restrict__ w,
                                       __half* __restrict__ th,
                                       __half* __restrict__ tl,
                                       int K, int N) {
  __shared__ float tile[32][33];
  int nx = blockIdx.x * 32 + threadIdx.x;
  int k0 = blockIdx.y * 32;
  for (int i = threadIdx.y; i < 32; i += 8)
    tile[i][threadIdx.x] = w[(size_t)(k0 + i) * N + nx];
  __syncthreads();
  for (int j = threadIdx.y; j < 32; j += 8) {
    int n = blockIdx.x * 32 + j;
    int kk = k0 + threadIdx.x;
    float f = tile[threadIdx.x][j];
    float h = f16_round(f);
    th[(size_t)n * K + kk] = __float2half(h);
    tl[(size_t)n * K + kk] = __float2half((f - h) * LO_SCALE);
  }
}

__global__ void rope_single_kernel(const float* __restrict__ t,
                                   const float* __restrict__ fcos,
                                   const float* __restrict__ fsin,
                                   __half* __restrict__ th, int nheads,
                                   float scale) {
  int idx = blockIdx.x * blockDim.x + threadIdx.x;
  int total = BATCH * SEQ * nheads * (HD / 2);
  if (idx >= total) return;
  int p = idx & 63;
  int rest = idx >> 6;
  int h = rest % nheads;
  rest /= nheads;
  int s = rest & (SEQ - 1);
  int b = rest >> 11;
  float c = fcos[s * 64 + p];
  float sn = fsin[s * 64 + p];
  size_t off = ((size_t)(b * SEQ + s) * nheads + h) * HD + p * 2;
  const float* base = t + off;
  float x0 = base[0], x1 = base[1];
  float o0 = (x0 * c - x1 * sn) * scale;
  float o1 = (x0 * sn + x1 * c) * scale;
  *(uint32_t*)(th + off) = pack_f16(o0, o1);
}

__global__ void rope_split_kernel(const float* __restrict__ t,
                                  const float* __restrict__ fcos,
                                  const float* __restrict__ fsin,
                                  __half* __restrict__ th,
                                  __half* __restrict__ tl, int nheads) {
  int idx = blockIdx.x * blockDim.x + threadIdx.x;
  int total = BATCH * SEQ * nheads * (HD / 2);
  if (idx >= total) return;
  int p = idx & 63;
  int rest = idx >> 6;
  int h = rest % nheads;
  rest /= nheads;
  int s = rest & (SEQ - 1);
  int b = rest >> 11;
  float c = fcos[s * 64 + p];
  float sn = fsin[s * 64 + p];
  size_t off = ((size_t)(b * SEQ + s) * nheads + h) * HD + p * 2;
  const float* base = t + off;
  float x0 = base[0], x1 = base[1];
  float o0 = x0 * c - x1 * sn;
  float o1 = x0 * sn + x1 * c;
  *(uint32_t*)(th + off) = pack_f16(o0, o1);
  *(uint32_t*)(tl + off) = pack_f16((o0 - f16_round(o0)) * LO_SCALE,
                                    (o1 - f16_round(o1)) * LO_SCALE);
}

// ---------------------------------------------------------------------------
// mma.sync fp16 2-product GEMM, 3-stage cp.async pipeline.
// MODE 0: plain fp32 C[M,N].  MODE 1: fused QKV epilogue (Q,K fp32; V split).
// 128x128 CTA tile, BK=32, 256 thr, 8 warps (warp tile 32x64).
// ---------------------------------------------------------------------------
#define SB 40
#define T2E (128 * SB)
#define STG_E (3 * T2E)
#define NSTG 3
#define GEMM_SMEM (NSTG * STG_E * 2)   // 92160 B

template <int MODE>
__global__ __launch_bounds__(256, 2) void gemm_mma_kernel(
    const __half* __restrict__ A, const __half* __restrict__ Bh,
    const __half* __restrict__ Bl, float* __restrict__ C, int N, int K,
    float* __restrict__ Cq, float* __restrict__ Ck,
    __half* __restrict__ Vh, __half* __restrict__ Vl) {
  extern __shared__ __half smb[];
  const int tid = threadIdx.x;
  const int lane = tid & 31;
  const int wid = tid >> 5;
  const int wm = wid & 3;
  const int wn = wid >> 2;
  const int m0 = blockIdx.y * 128;
  const int n0 = blockIdx.x * 128;
  const uint32_t sbase = smem_u32(smb);

  const uint32_t OA = 0, OBH = T2E, OBL = 2 * T2E;
  const int BN = (MODE == 1) ? QKVN : N;   // B row count for addressing

  float acc[2][8][4];
#pragma unroll
  for (int i = 0; i < 2; ++i)
#pragma unroll
    for (int j = 0; j < 8; ++j)
#pragma unroll
      for (int q = 0; q < 4; ++q) acc[i][j][q] = 0.f;

  const int a_row = lane & 15;
  const int a_col = (lane >> 4) * 8;
  const int b_row = (lane & 7) + ((lane & 16) >> 1);
  const int b_col = lane & 8;

  const int l_r = tid >> 2;
  const int l_c = (tid & 3) * 8;

  const int nchunks = K >> 5;
  (void)BN;

  // prologue: chunks 0 and 1
#pragma unroll
  for (int pc = 0; pc < 2; ++pc) {
    const int k0g = pc << 5;
    const uint32_t stb = sbase + pc * (STG_E * 2);
#pragma unroll
    for (int it = 0; it < 2; ++it) {
      int r = l_r + it * 64;
      const size_t ga = (size_t)(m0 + r) * K + k0g + l_c;
      const size_t gb = (size_t)(n0 + r) * K + k0g + l_c;
      uint32_t so = (uint32_t)(r * SB + l_c) * 2;
      cpa16(stb + OA * 2 + so, A + ga);
      cpa16(stb + OBH * 2 + so, Bh + gb);
      cpa16(stb + OBL * 2 + so, Bl + gb);
    }
    cpa_commit();
  }

  for (int c = 0; c < nchunks; ++c) {
    if (c + 2 < nchunks) {
      cpa_wait1();
      __syncthreads();                 // compute c-1 done everywhere
      const int k0g = (c + 2) << 5;
      const uint32_t stb = sbase + ((c + 2) % NSTG) * (STG_E * 2);
#pragma unroll
      for (int it = 0; it < 2; ++it) {
        int r = l_r + it * 64;
        const size_t ga = (size_t)(m0 + r) * K + k0g + l_c;
        const size_t gb = (size_t)(n0 + r) * K + k0g + l_c;
        uint32_t so = (uint32_t)(r * SB + l_c) * 2;
        cpa16(stb + OA * 2 + so, A + ga);
        cpa16(stb + OBH * 2 + so, Bh + gb);
        cpa16(stb + OBL * 2 + so, Bl + gb);
      }
      cpa_commit();
      cpa_wait1();                     // chunk c done (c+1, c+2 may pend)
    } else {
      cpa_wait0();
    }
    __syncthreads();

    const uint32_t stg = sbase + (c % NSTG) * (STG_E * 2);
#pragma unroll
    for (int s = 0; s < 2; ++s) {
      const int k0 = s * 16;
      uint32_t af[2][4], afs[2][4];
#pragma unroll
      for (int mt = 0; mt < 2; ++mt) {
        uint32_t off = (uint32_t)((wm * 32 + mt * 16 + a_row) * SB + k0 + a_col) * 2;
        ldsm_x4(stg + OA * 2 + off, af[mt]);
#pragma unroll
        for (int qq = 0; qq < 4; ++qq) afs[mt][qq] = hscale(af[mt][qq]);
      }
#pragma unroll
      for (int nt2 = 0; nt2 < 4; ++nt2) {
        uint32_t bh[4], bl[4];
        uint32_t off = (uint32_t)((wn * 64 + nt2 * 16 + b_row) * SB + k0 + b_col) * 2;
        ldsm_x4(stg + OBH * 2 + off, bh);
        ldsm_x4(stg + OBL * 2 + off, bl);
#pragma unroll
        for (int mt = 0; mt < 2; ++mt) {
          mma_f16(acc[mt][nt2 * 2], af[mt], bh);
          mma_f16(acc[mt][nt2 * 2], afs[mt], bl);
          mma_f16(acc[mt][nt2 * 2 + 1], af[mt], bh + 2);
          mma_f16(acc[mt][nt2 * 2 + 1], afs[mt], bl + 2);
        }
      }
    }
    __syncthreads();                   // stage free for reuse
  }

#pragma unroll
  for (int mt = 0; mt < 2; ++mt) {
    int r0 = m0 + wm * 32 + mt * 16 + (lane >> 2);
#pragma unroll
    for (int nt = 0; nt < 8; ++nt) {
      int col = n0 + wn * 64 + nt * 8 + (lane & 3) * 2;
      float a0 = acc[mt][nt][0], a1 = acc[mt][nt][1];
      float b0 = acc[mt][nt][2], b1 = acc[mt][nt][3];
      if (MODE == 0) {
        float2 v0 = {a0, a1};
        float2 v1 = {b0, b1};
        *(float2*)(C + (size_t)r0 * N + col) = v0;
        *(float2*)(C + (size_t)(r0 + 8) * N + col) = v1;
      } else {
        if (col < DMODEL) {                    // Q region, fp32, stride 2048
          float2 v0 = {a0, a1};
          float2 v1 = {b0, b1};
          *(float2*)(Cq + (size_t)r0 * DMODEL + col) = v0;
          *(float2*)(Cq + (size_t)(r0 + 8) * DMODEL + col) = v1;
        } else if (col < DMODEL + KVDIM) {     // K region, fp32, stride 512
          int kc = col - DMODEL;
          float2 v0 = {a0, a1};
          float2 v1 = {b0, b1};
          *(float2*)(Ck + (size_t)r0 * KVDIM + kc) = v0;
          *(float2*)(Ck + (size_t)(r0 + 8) * KVDIM + kc) = v1;
        } else {                               // V region, split fp16
          int vc = col - DMODEL - KVDIM;
          *(uint32_t*)(Vh + (size_t)r0 * KVDIM + vc) = pack_f16(a0, a1);
          *(uint32_t*)(Vl + (size_t)r0 * KVDIM + vc) =
              pack_f16((a0 - f16_round(a0)) * LO_SCALE,
                       (a1 - f16_round(a1)) * LO_SCALE);
          *(uint32_t*)(Vh + (size_t)(r0 + 8) * KVDIM + vc) = pack_f16(b0, b1);
          *(uint32_t*)(Vl + (size_t)(r0 + 8) * KVDIM + vc) =
              pack_f16((b0 - f16_round(b0)) * LO_SCALE,
                       (b1 - f16_round(b1)) * LO_SCALE);
        }
      }
    }
  }
}

// ---------------------------------------------------------------------------
// Tensor-core flash attention, fp16 2-product, causal.
// BLOCK_M=128 (8 warps x m16), BLOCK_N=64, D=128. KV double-buffered.
// ---------------------------------------------------------------------------
#define FSD 136                        // smem stride (elements)
#define FTE (64 * FSD)                 // elements per 64-row tile
#define QTE (128 * FSD)                // Q tile (128 rows)
#define KVSTG (4 * FTE)                // Kh,Kl,Vh,Vl per stage
#define FA_SMEM ((QTE + 2 * KVSTG) * 2)   // 174080 B

__global__ __launch_bounds__(256) void fa_mma_kernel(
    const __half* __restrict__ qh, const __half* __restrict__ kh,
    const __half* __restrict__ kl, const __half* __restrict__ vh,
    const __half* __restrict__ vl, __half* __restrict__ ao) {
  extern __shared__ __half fsm[];
  const uint32_t sbase = smem_u32(fsm);
  const int tid = threadIdx.x;
  const int lane = tid & 31;
  const int w = tid >> 5;

  const int mt = gridDim.x - 1 - blockIdx.x;   // heavy tiles first
  const int m0 = mt * 128;
  const int h = blockIdx.y;
  const int b = blockIdx.z;
  const int g = h >> 2;
  const int tmax = 2 * mt + 1;

  const uint32_t QO = 0;
  const uint32_t KV0 = QTE;            // stage s at KV0 + s*KVSTG
  const int lr = tid >> 4;             // 0..15
  const int lc = (tid & 15) * 8;

  // prologue: Q tile + KV tile 0
  {
#pragma unroll
    for (int it = 0; it < 8; ++it) {
      int row = lr + it * 16;
      size_t gi = ((size_t)(b * SEQ + m0 + row) * NH + h) * HD + lc;
      cpa16(sbase + (QO + (uint32_t)(row * FSD + lc)) * 2, qh + gi);
    }
    cpa_commit();
#pragma unroll
    for (int it = 0; it < 4; ++it) {
      int row = lr + it * 16;
      size_t gi = ((size_t)(b * SEQ + row) * NKV + g) * HD + lc;
      uint32_t e = (uint32_t)(row * FSD + lc) * 2;
      uint32_t st = sbase + KV0 * 2;
      cpa16(st + (0 * FTE) * 2 + e, kh + gi);
      cpa16(st + (1 * FTE) * 2 + e, kl + gi);
      cpa16(st + (2 * FTE) * 2 + e, vh + gi);
      cpa16(st + (3 * FTE) * 2 + e, vl + gi);
    }
    cpa_commit();
  }

  float m_lo = -1e30f, m_hi = -1e30f, l_lo = 0.f, l_hi = 0.f;
  float oacc[16][4];
#pragma unroll
  for (int i = 0; i < 16; ++i)
#pragma unroll
    for (int j = 0; j < 4; ++j) oacc[i][j] = 0.f;

  const int a_row = lane & 15;
  const int a_col = (lane >> 4) * 8;
  const int b_row = (lane & 7) + ((lane & 16) >> 1);
  const int b_col = lane & 8;

  for (int t = 0; t <= tmax; ++t) {
    const int n0 = t * 64;
    __syncthreads();                   // compute t-1 done: stage (t+1)&1 free
    if (t + 1 <= tmax) {
      const int nn0 = (t + 1) * 64;
      uint32_t st = sbase + (KV0 + ((t + 1) & 1) * KVSTG) * 2;
#pragma unroll
      for (int it = 0; it < 4; ++it) {
        int row = lr + it * 16;
        size_t gi = ((size_t)(b * SEQ + nn0 + row) * NKV + g) * HD + lc;
        uint32_t e = (uint32_t)(row * FSD + lc) * 2;
        cpa16(st + (0 * FTE) * 2 + e, kh + gi);
        cpa16(st + (1 * FTE) * 2 + e, kl + gi);
        cpa16(st + (2 * FTE) * 2 + e, vh + gi);
        cpa16(st + (3 * FTE) * 2 + e, vl + gi);
      }
      cpa_commit();
      cpa_wait1();                     // tile t (and Q) complete
    } else {
      cpa_wait0();
    }
    __syncthreads();

    const uint32_t KS = KV0 + (t & 1) * KVSTG;

    // --- S = Q @ (Kh + Kl*2^-10)^T ---
    float sacc[8][4];
#pragma unroll
    for (int i = 0; i < 8; ++i)
#pragma unroll
      for (int j = 0; j < 4; ++j) sacc[i][j] = 0.f;

#pragma unroll
    for (int kc = 0; kc < 8; ++kc) {
      uint32_t aq_off = (uint32_t)((w * 16 + a_row) * FSD + kc * 16 + a_col) * 2;
      uint32_t aq[4], aqs[4];
      ldsm_x4(sbase + QO * 2 + aq_off, aq);
#pragma unroll
      for (int qq = 0; qq < 4; ++qq) aqs[qq] = hscale(aq[qq]);
#pragma unroll
      for (int np = 0; np < 4; ++np) {
        uint32_t bo = (uint32_t)((np * 16 + b_row) * FSD + kc * 16 + b_col) * 2;
        uint32_t bhf[4], blf[4];
        ldsm_x4(sbase + (KS + 0 * FTE) * 2 + bo, bhf);
        ldsm_x4(sbase + (KS + 1 * FTE) * 2 + bo, blf);
        mma_f16(sacc[np * 2], aq, bhf);
        mma_f16(sacc[np * 2], aqs, blf);
        mma_f16(sacc[np * 2 + 1], aq, bhf + 2);
        mma_f16(sacc[np * 2 + 1], aqs, blf + 2);
      }
    }

    // --- causal mask (only tiles crossing the diagonal for this warp) ---
    {
      int row_lo = m0 + w * 16 + (lane >> 2);
      if (n0 + 63 > row_lo) {
        int row_hi = row_lo + 8;
#pragma unroll
        for (int nt = 0; nt < 8; ++nt) {
          int c0 = n0 + nt * 8 + (lane & 3) * 2;
          if (c0 > row_lo) sacc[nt][0] = -1e30f;
          if (c0 + 1 > row_lo) sacc[nt][1] = -1e30f;
          if (c0 > row_hi) sacc[nt][2] = -1e30f;
          if (c0 + 1 > row_hi) sacc[nt][3] = -1e30f;
        }
      }
    }

    // --- online softmax ---
    float rmax_lo = -1e30f, rmax_hi = -1e30f;
#pragma unroll
    for (int nt = 0; nt < 8; ++nt) {
      rmax_lo = fmaxf(rmax_lo, fmaxf(sacc[nt][0], sacc[nt][1]));
      rmax_hi = fmaxf(rmax_hi, fmaxf(sacc[nt][2], sacc[nt][3]));
    }
#pragma unroll
    for (int d = 1; d < 4; d <<= 1) {
      rmax_lo = fmaxf(rmax_lo, __shfl_xor_sync(0xffffffffu, rmax_lo, d));
      rmax_hi = fmaxf(rmax_hi, __shfl_xor_sync(0xffffffffu, rmax_hi, d));
    }
    float mn_lo = fmaxf(m_lo, rmax_lo);
    float mn_hi = fmaxf(m_hi, rmax_hi);
    float f_lo = __expf(m_lo - mn_lo);
    float f_hi = __expf(m_hi - mn_hi);
    m_lo = mn_lo; m_hi = mn_hi;

    float rsum_lo = 0.f, rsum_hi = 0.f;
#pragma unroll
    for (int nt = 0; nt < 8; ++nt) {
      sacc[nt][0] = __expf(sacc[nt][0] - mn_lo);
      sacc[nt][1] = __expf(sacc[nt][1] - mn_lo);
      sacc[nt][2] = __expf(sacc[nt][2] - mn_hi);
      sacc[nt][3] = __expf(sacc[nt][3] - mn_hi);
      rsum_lo += sacc[nt][0] + sacc[nt][1];
      rsum_hi += sacc[nt][2] + sacc[nt][3];
    }
#pragma unroll
    for (int d = 1; d < 4; d <<= 1) {
      rsum_lo += __shfl_xor_sync(0xffffffffu, rsum_lo, d);
      rsum_hi += __shfl_xor_sync(0xffffffffu, rsum_hi, d);
    }
    l_lo = l_lo * f_lo + rsum_lo;
    l_hi = l_hi * f_hi + rsum_hi;
#pragma unroll
    for (int i = 0; i < 16; ++i) {
      oacc[i][0] *= f_lo; oacc[i][1] *= f_lo;
      oacc[i][2] *= f_hi; oacc[i][3] *= f_hi;
    }

    // --- O += P @ (Vh + Vl*2^-10) ---
#pragma unroll
    for (int kt = 0; kt < 4; ++kt) {
      const float* s0 = sacc[2 * kt];
      const float* s1 = sacc[2 * kt + 1];
      uint32_t ph[4], ps[4];
      ph[0] = pack_f16(s0[0], s0[1]);
      ph[1] = pack_f16(s0[2], s0[3]);
      ph[2] = pack_f16(s1[0], s1[1]);
      ph[3] = pack_f16(s1[2], s1[3]);
      ps[0] = pack_f16(s0[0] * INV_LO_SCALE, s0[1] * INV_LO_SCALE);
      ps[1] = pack_f16(s0[2] * INV_LO_SCALE, s0[3] * INV_LO_SCALE);
      ps[2] = pack_f16(s1[0] * INV_LO_SCALE, s1[1] * INV_LO_SCALE);
      ps[3] = pack_f16(s1[2] * INV_LO_SCALE, s1[3] * INV_LO_SCALE);
#pragma unroll
      for (int dp = 0; dp < 8; ++dp) {
        uint32_t vo = (uint32_t)((kt * 16 + (lane & 15)) * FSD + dp * 16 +
                                 ((lane >> 4) << 3)) * 2;
        uint32_t vhf[4], vlf[4];
        ldsm_x4_t(sbase + (KS + 2 * FTE) * 2 + vo, vhf);
        ldsm_x4_t(sbase + (KS + 3 * FTE) * 2 + vo, vlf);
        mma_f16(oacc[dp * 2], ph, vhf);
        mma_f16(oacc[dp * 2], ps, vlf);
        mma_f16(oacc[dp * 2 + 1], ph, vhf + 2);
        mma_f16(oacc[dp * 2 + 1], ps, vlf + 2);
      }
    }
  }

  // --- epilogue: normalize, round to fp16, write [b,s,h,d] ---
  float inv_lo = 1.f / l_lo;
  float inv_hi = 1.f / l_hi;
  int r_lo = m0 + w * 16 + (lane >> 2);
  int r_hi = r_lo + 8;
#pragma unroll
  for (int dt = 0; dt < 16; ++dt) {
    int col = dt * 8 + (lane & 3) * 2;
    size_t i0 = ((size_t)(b * SEQ + r_lo) * NH + h) * HD + col;
    size_t i1 = ((size_t)(b * SEQ + r_hi) * NH + h) * HD + col;
    *(uint32_t*)(ao + i0) = pack_f16(oacc[dt][0] * inv_lo, oacc[dt][1] * inv_lo);
    *(uint32_t*)(ao + i1) = pack_f16(oacc[dt][2] * inv_hi, oacc[dt][3] * inv_hi);
  }
}

// ---------------------------------------------------------------------------
// Launch
// ---------------------------------------------------------------------------
extern "C" void kernel_launch(void* const* d_in, const int* in_sizes, int n_in,
                              void* d_out, int out_size) {
  const float* x    = (const float*)d_in[0];
  const float* fcos = (const float*)d_in[1];
  const float* fsin = (const float*)d_in[2];
  // d_in[3] = mask (causal mask applied analytically)
  const float* wq = (const float*)d_in[4];
  const float* wk = (const float*)d_in[5];
  const float* wv = (const float*)d_in[6];
  const float* wo = (const float*)d_in[7];
  float* out = (float*)d_out;

  float *q, *k;
  cudaGetSymbolAddress((void**)&q, g_q);
  cudaGetSymbolAddress((void**)&k, g_k);
  __half *xh, *aoh, *qh, *kh, *kl, *vh, *vl;
  __half *wqkvh, *wqkvl, *woh, *wol;
  cudaGetSymbolAddress((void**)&xh, g_xh);
  cudaGetSymbolAddress((void**)&aoh, g_aoh);
  cudaGetSymbolAddress((void**)&qh, g_qh);
  cudaGetSymbolAddress((void**)&kh, g_kh);
  cudaGetSymbolAddress((void**)&kl, g_kl);
  cudaGetSymbolAddress((void**)&vh, g_vh);
  cudaGetSymbolAddress((void**)&vl, g_vl);
  cudaGetSymbolAddress((void**)&wqkvh, g_wqkv_h);
  cudaGetSymbolAddress((void**)&wqkvl, g_wqkv_l);
  cudaGetSymbolAddress((void**)&woh, g_wo_h);
  cudaGetSymbolAddress((void**)&wol, g_wo_l);

  static bool attr_done = false;
  if (!attr_done) {
    cudaFuncSetAttribute(gemm_mma_kernel<0>,
                         cudaFuncAttributeMaxDynamicSharedMemorySize, GEMM_SMEM);
    cudaFuncSetAttribute(gemm_mma_kernel<1>,
                         cudaFuncAttributeMaxDynamicSharedMemorySize, GEMM_SMEM);
    cudaFuncSetAttribute(fa_mma_kernel,
                         cudaFuncAttributeMaxDynamicSharedMemorySize, FA_SMEM);
    attr_done = true;
  }

  // round x / transpose+split weights into combined QKV + wo
  {
    int nx = MTOK * DMODEL;
    round_kernel<<<(nx + 255) / 256, 256>>>(x, xh, nx);
    dim3 blk(32, 8);
    transpose_split_kernel<<<dim3(DMODEL / 32, DMODEL / 32), blk>>>(
        wq, wqkvh, wqkvl, DMODEL, DMODEL);
    transpose_split_kernel<<<dim3(KVDIM / 32, DMODEL / 32), blk>>>(
        wk, wqkvh + (size_t)DMODEL * DMODEL, wqkvl + (size_t)DMODEL * DMODEL,
        DMODEL, KVDIM);
    transpose_split_kernel<<<dim3(KVDIM / 32, DMODEL / 32), blk>>>(
        wv, wqkvh + (size_t)(DMODEL + KVDIM) * DMODEL,
        wqkvl + (size_t)(DMODEL + KVDIM) * DMODEL, DMODEL, KVDIM);
    transpose_split_kernel<<<dim3(DMODEL / 32, DMODEL / 32), blk>>>(
        wo, woh, wol, DMODEL, DMODEL);
  }

  // fused QKV projection (one launch, 768 CTAs)
  gemm_mma_kernel<1><<<dim3(QKVN / 128, MTOK / 128), 256, GEMM_SMEM>>>(
      xh, wqkvh, wqkvl, nullptr, QKVN, DMODEL, q, k, vh, vl);

  // RoPE: Q single (pre-scaled), K split
  {
    const float scale = 0.08838834764831845f;  // 1/sqrt(128)
    int tq = BATCH * SEQ * NH * (HD / 2);
    rope_single_kernel<<<(tq + 255) / 256, 256>>>(q, fcos, fsin, qh, NH, scale);
    int tk = BATCH * SEQ * NKV * (HD / 2);
    rope_split_kernel<<<(tk + 255) / 256, 256>>>(k, fcos, fsin, kh, kl, NKV);
  }

  // Tensor-core flash attention (BLOCK_M=128, KV double-buffered)
  fa_mma_kernel<<<dim3(SEQ / 128, NH, BATCH), 256, FA_SMEM>>>(
      qh, kh, kl, vh, vl, aoh);

  // Output projection
  gemm_mma_kernel<0><<<dim3(DMODEL / 128, MTOK / 128), 256, GEMM_SMEM>>>(
      aoh, woh, wol, out, DMODEL, DMODEL, nullptr, nullptr, nullptr, nullptr);
}

// round 12
// speedup vs baseline: 1.5375x; 1.5375x over previous
#include <cuda_runtime.h>
#include <cuda_fp16.h>
#include <cstdint>
#include <math.h>

// Problem dims (fixed by reference)
#define BATCH 2
#define SEQ 2048
#define DMODEL 2048
#define NH 16
#define NKV 4
#define HD 128
#define MTOK (BATCH * SEQ)          // 4096 tokens
#define KVDIM (NKV * HD)            // 512
#define QKVN (DMODEL + 2 * KVDIM)   // 3072

// ---------------------------------------------------------------------------
// Scratch (device globals; runtime allocation is forbidden)
// ---------------------------------------------------------------------------
__device__ float g_q[MTOK * NH * HD];
__device__ float g_k[MTOK * KVDIM];

__device__ __half g_xh[MTOK * DMODEL];
__device__ __half g_aoh[MTOK * DMODEL];
__device__ __half g_qh[MTOK * NH * HD];
__device__ __half g_kh[MTOK * KVDIM];
__device__ __half g_kl[MTOK * KVDIM];
__device__ __half g_vh[MTOK * KVDIM];
__device__ __half g_vl[MTOK * KVDIM];
// combined QKV weights [3072, 2048] (rows: wq 0-2047, wk 2048-2559, wv 2560-3071)
__device__ __half g_wqkv_h[QKVN * DMODEL];
__device__ __half g_wqkv_l[QKVN * DMODEL];
__device__ __half g_wo_h[DMODEL * DMODEL];
__device__ __half g_wo_l[DMODEL * DMODEL];

#define LO_SCALE 1024.0f
#define INV_LO_SCALE 0.0009765625f
#define HSC2 0x14001400u                     // fp16x2 constant 2^-10

// ---------------------------------------------------------------------------
// helpers
// ---------------------------------------------------------------------------
__device__ __forceinline__ uint32_t smem_u32(const void* p) {
  uint32_t a;
  asm("{ .reg .u64 t; cvta.to.shared.u64 t, %1; cvt.u32.u64 %0, t; }"
      : "=r"(a) : "l"(p));
  return a;
}
__device__ __forceinline__ void cpa16(uint32_t s, const void* g) {
  asm volatile("cp.async.cg.shared.global [%0], [%1], 16;"
               :: "r"(s), "l"(g) : "memory");
}
__device__ __forceinline__ void cpa_commit() {
  asm volatile("cp.async.commit_group;" ::: "memory");
}
__device__ __forceinline__ void cpa_wait0() {
  asm volatile("cp.async.wait_group 0;" ::: "memory");
}
__device__ __forceinline__ void ldsm_x4(uint32_t addr, uint32_t* r) {
  asm volatile("ldmatrix.sync.aligned.m8n8.x4.shared.b16 {%0,%1,%2,%3}, [%4];"
               : "=r"(r[0]), "=r"(r[1]), "=r"(r[2]), "=r"(r[3]) : "r"(addr));
}
__device__ __forceinline__ void ldsm_x4_t(uint32_t addr, uint32_t* r) {
  asm volatile("ldmatrix.sync.aligned.m8n8.x4.trans.shared.b16 {%0,%1,%2,%3}, [%4];"
               : "=r"(r[0]), "=r"(r[1]), "=r"(r[2]), "=r"(r[3]) : "r"(addr));
}
__device__ __forceinline__ void mma_f16(float* d, const uint32_t* a,
                                        const uint32_t* b) {
  asm volatile(
      "mma.sync.aligned.m16n8k16.row.col.f32.f16.f16.f32 "
      "{%0,%1,%2,%3}, {%4,%5,%6,%7}, {%8,%9}, {%0,%1,%2,%3};"
      : "+f"(d[0]), "+f"(d[1]), "+f"(d[2]), "+f"(d[3])
      : "r"(a[0]), "r"(a[1]), "r"(a[2]), "r"(a[3]), "r"(b[0]), "r"(b[1]));
}
__device__ __forceinline__ uint32_t pack_f16(float a, float b) {
  uint32_t r;
  asm("cvt.rn.f16x2.f32 %0, %1, %2;" : "=r"(r) : "f"(b), "f"(a));
  return r;
}
__device__ __forceinline__ float f16_round(float f) {
  return __half2float(__float2half(f));
}
__device__ __forceinline__ uint32_t hscale(uint32_t x) {
  uint32_t r;
  asm("mul.f16x2 %0, %1, %2;" : "=r"(r) : "r"(x), "r"(HSC2));
  return r;
}

// ---------------------------------------------------------------------------
// Conversion kernels
// ---------------------------------------------------------------------------
__global__ void round_kernel(const float* __restrict__ src,
                             __half* __restrict__ dst, int n) {
  int i = blockIdx.x * blockDim.x + threadIdx.x;
  if (i >= n) return;
  dst[i] = __float2half(src[i]);
}

__global__ void transpose_split_kernel(const float* __restrict__ w,
                                       __half* __restrict__ th,
                                       __half* __restrict__ tl,
                                       int K, int N) {
  __shared__ float tile[32][33];
  int nx = blockIdx.x * 32 + threadIdx.x;
  int k0 = blockIdx.y * 32;
  for (int i = threadIdx.y; i < 32; i += 8)
    tile[i][threadIdx.x] = w[(size_t)(k0 + i) * N + nx];
  __syncthreads();
  for (int j = threadIdx.y; j < 32; j += 8) {
    int n = blockIdx.x * 32 + j;
    int kk = k0 + threadIdx.x;
    float f = tile[threadIdx.x][j];
    float h = f16_round(f);
    th[(size_t)n * K + kk] = __float2half(h);
    tl[(size_t)n * K + kk] = __float2half((f - h) * LO_SCALE);
  }
}

__global__ void rope_single_kernel(const float* __restrict__ t,
                                   const float* __restrict__ fcos,
                                   const float* __restrict__ fsin,
                                   __half* __restrict__ th, int nheads,
                                   float scale) {
  int idx = blockIdx.x * blockDim.x + threadIdx.x;
  int total = BATCH * SEQ * nheads * (HD / 2);
  if (idx >= total) return;
  int p = idx & 63;
  int rest = idx >> 6;
  int h = rest % nheads;
  rest /= nheads;
  int s = rest & (SEQ - 1);
  int b = rest >> 11;
  float c = fcos[s * 64 + p];
  float sn = fsin[s * 64 + p];
  size_t off = ((size_t)(b * SEQ + s) * nheads + h) * HD + p * 2;
  const float* base = t + off;
  float x0 = base[0], x1 = base[1];
  float o0 = (x0 * c - x1 * sn) * scale;
  float o1 = (x0 * sn + x1 * c) * scale;
  *(uint32_t*)(th + off) = pack_f16(o0, o1);
}

__global__ void rope_split_kernel(const float* __restrict__ t,
                                  const float* __restrict__ fcos,
                                  const float* __restrict__ fsin,
                                  __half* __restrict__ th,
                                  __half* __restrict__ tl, int nheads) {
  int idx = blockIdx.x * blockDim.x + threadIdx.x;
  int total = BATCH * SEQ * nheads * (HD / 2);
  if (idx >= total) return;
  int p = idx & 63;
  int rest = idx >> 6;
  int h = rest % nheads;
  rest /= nheads;
  int s = rest & (SEQ - 1);
  int b = rest >> 11;
  float c = fcos[s * 64 + p];
  float sn = fsin[s * 64 + p];
  size_t off = ((size_t)(b * SEQ + s) * nheads + h) * HD + p * 2;
  const float* base = t + off;
  float x0 = base[0], x1 = base[1];
  float o0 = x0 * c - x1 * sn;
  float o1 = x0 * sn + x1 * c;
  *(uint32_t*)(th + off) = pack_f16(o0, o1);
  *(uint32_t*)(tl + off) = pack_f16((o0 - f16_round(o0)) * LO_SCALE,
                                    (o1 - f16_round(o1)) * LO_SCALE);
}

// ---------------------------------------------------------------------------
// mma.sync fp16 2-product GEMM, 2-stage cp.async pipeline (R9 structure).
// MODE 0: plain fp32 C[M,N].  MODE 1: fused QKV epilogue (Q,K fp32; V split).
// 128x128 CTA tile, BK=32, 256 thr, 8 warps (warp tile 32x64).
// ---------------------------------------------------------------------------
#define SB 40
#define T2E (128 * SB)
#define STG_E (3 * T2E)
#define GEMM_SMEM (2 * STG_E * 2)      // 61440 B

template <int MODE>
__global__ __launch_bounds__(256, 2) void gemm_mma_kernel(
    const __half* __restrict__ A, const __half* __restrict__ Bh,
    const __half* __restrict__ Bl, float* __restrict__ C, int N, int K,
    float* __restrict__ Cq, float* __restrict__ Ck,
    __half* __restrict__ Vh, __half* __restrict__ Vl) {
  extern __shared__ __half smb[];
  const int tid = threadIdx.x;
  const int lane = tid & 31;
  const int wid = tid >> 5;
  const int wm = wid & 3;
  const int wn = wid >> 2;
  const int m0 = blockIdx.y * 128;
  const int n0 = blockIdx.x * 128;
  const uint32_t sbase = smem_u32(smb);

  const uint32_t OA = 0, OBH = T2E, OBL = 2 * T2E;

  float acc[2][8][4];
#pragma unroll
  for (int i = 0; i < 2; ++i)
#pragma unroll
    for (int j = 0; j < 8; ++j)
#pragma unroll
      for (int q = 0; q < 4; ++q) acc[i][j][q] = 0.f;

  const int a_row = lane & 15;
  const int a_col = (lane >> 4) * 8;
  const int b_row = (lane & 7) + ((lane & 16) >> 1);
  const int b_col = lane & 8;

  const int l_r = tid >> 2;
  const int l_c = (tid & 3) * 8;

  const int nchunks = K >> 5;

  {
#pragma unroll
    for (int it = 0; it < 2; ++it) {
      int r = l_r + it * 64;
      const size_t ga = (size_t)(m0 + r) * K + l_c;
      const size_t gb = (size_t)(n0 + r) * K + l_c;
      uint32_t so = (uint32_t)(r * SB + l_c) * 2;
      cpa16(sbase + OA * 2 + so, A + ga);
      cpa16(sbase + OBH * 2 + so, Bh + gb);
      cpa16(sbase + OBL * 2 + so, Bl + gb);
    }
    cpa_commit();
  }

  for (int c = 0; c < nchunks; ++c) {
    cpa_wait0();
    __syncthreads();
    if (c + 1 < nchunks) {
      const int k0g = (c + 1) << 5;
      const uint32_t stb = sbase + ((c + 1) & 1) * (STG_E * 2);
#pragma unroll
      for (int it = 0; it < 2; ++it) {
        int r = l_r + it * 64;
        const size_t ga = (size_t)(m0 + r) * K + k0g + l_c;
        const size_t gb = (size_t)(n0 + r) * K + k0g + l_c;
        uint32_t so = (uint32_t)(r * SB + l_c) * 2;
        cpa16(stb + OA * 2 + so, A + ga);
        cpa16(stb + OBH * 2 + so, Bh + gb);
        cpa16(stb + OBL * 2 + so, Bl + gb);
      }
      cpa_commit();
    }

    const uint32_t stg = sbase + (c & 1) * (STG_E * 2);
#pragma unroll
    for (int s = 0; s < 2; ++s) {
      const int k0 = s * 16;
      uint32_t af[2][4], afs[2][4];
#pragma unroll
      for (int mt = 0; mt < 2; ++mt) {
        uint32_t off = (uint32_t)((wm * 32 + mt * 16 + a_row) * SB + k0 + a_col) * 2;
        ldsm_x4(stg + OA * 2 + off, af[mt]);
#pragma unroll
        for (int qq = 0; qq < 4; ++qq) afs[mt][qq] = hscale(af[mt][qq]);
      }
#pragma unroll
      for (int nt2 = 0; nt2 < 4; ++nt2) {
        uint32_t bh[4], bl[4];
        uint32_t off = (uint32_t)((wn * 64 + nt2 * 16 + b_row) * SB + k0 + b_col) * 2;
        ldsm_x4(stg + OBH * 2 + off, bh);
        ldsm_x4(stg + OBL * 2 + off, bl);
#pragma unroll
        for (int mt = 0; mt < 2; ++mt) {
          mma_f16(acc[mt][nt2 * 2], af[mt], bh);
          mma_f16(acc[mt][nt2 * 2], afs[mt], bl);
          mma_f16(acc[mt][nt2 * 2 + 1], af[mt], bh + 2);
          mma_f16(acc[mt][nt2 * 2 + 1], afs[mt], bl + 2);
        }
      }
    }
  }

#pragma unroll
  for (int mt = 0; mt < 2; ++mt) {
    int r0 = m0 + wm * 32 + mt * 16 + (lane >> 2);
#pragma unroll
    for (int nt = 0; nt < 8; ++nt) {
      int col = n0 + wn * 64 + nt * 8 + (lane & 3) * 2;
      float a0 = acc[mt][nt][0], a1 = acc[mt][nt][1];
      float b0 = acc[mt][nt][2], b1 = acc[mt][nt][3];
      if (MODE == 0) {
        float2 v0 = {a0, a1};
        float2 v1 = {b0, b1};
        *(float2*)(C + (size_t)r0 * N + col) = v0;
        *(float2*)(C + (size_t)(r0 + 8) * N + col) = v1;
      } else {
        if (col < DMODEL) {                    // Q region, fp32, stride 2048
          float2 v0 = {a0, a1};
          float2 v1 = {b0, b1};
          *(float2*)(Cq + (size_t)r0 * DMODEL + col) = v0;
          *(float2*)(Cq + (size_t)(r0 + 8) * DMODEL + col) = v1;
        } else if (col < DMODEL + KVDIM) {     // K region, fp32, stride 512
          int kc = col - DMODEL;
          float2 v0 = {a0, a1};
          float2 v1 = {b0, b1};
          *(float2*)(Ck + (size_t)r0 * KVDIM + kc) = v0;
          *(float2*)(Ck + (size_t)(r0 + 8) * KVDIM + kc) = v1;
        } else {                               // V region, split fp16
          int vc = col - DMODEL - KVDIM;
          *(uint32_t*)(Vh + (size_t)r0 * KVDIM + vc) = pack_f16(a0, a1);
          *(uint32_t*)(Vl + (size_t)r0 * KVDIM + vc) =
              pack_f16((a0 - f16_round(a0)) * LO_SCALE,
                       (a1 - f16_round(a1)) * LO_SCALE);
          *(uint32_t*)(Vh + (size_t)(r0 + 8) * KVDIM + vc) = pack_f16(b0, b1);
          *(uint32_t*)(Vl + (size_t)(r0 + 8) * KVDIM + vc) =
              pack_f16((b0 - f16_round(b0)) * LO_SCALE,
                       (b1 - f16_round(b1)) * LO_SCALE);
        }
      }
    }
  }
}

// ---------------------------------------------------------------------------
// Tensor-core flash attention, fp16 2-product, causal (R9 structure).
// BLOCK_M=64 (4 warps x m16), BLOCK_N=64, D=128. 87 KB smem -> 2 CTAs/SM.
// ---------------------------------------------------------------------------
#define FSD 136                       // smem stride (elements)
#define FTE (64 * FSD)                // elements per tile
#define FA_SMEM (5 * FTE * 2)         // Q,Kh,Kl,Vh,Vl = 87040 B

__global__ __launch_bounds__(128) void fa_mma_kernel(
    const __half* __restrict__ qh, const __half* __restrict__ kh,
    const __half* __restrict__ kl, const __half* __restrict__ vh,
    const __half* __restrict__ vl, __half* __restrict__ ao) {
  extern __shared__ __half fsm[];
  const uint32_t sbase = smem_u32(fsm);
  const int tid = threadIdx.x;
  const int lane = tid & 31;
  const int w = tid >> 5;

  const int mt = gridDim.x - 1 - blockIdx.x;   // heavy tiles first
  const int m0 = mt * 64;
  const int h = blockIdx.y;
  const int b = blockIdx.z;
  const int g = h >> 2;

  const uint32_t QO = 0, KHO = FTE, KLO = 2 * FTE, VHO = 3 * FTE,
                 VLO = 4 * FTE;

  // --- async-load Q tile (pre-scaled fp16) ---
  {
    const int r = tid >> 4;
    const int cvec = (tid & 15) * 8;
#pragma unroll
    for (int it = 0; it < 8; ++it) {
      int row = r + it * 8;
      size_t gi = ((size_t)(b * SEQ + m0 + row) * NH + h) * HD + cvec;
      cpa16(sbase + (QO + (uint32_t)(row * FSD + cvec)) * 2, qh + gi);
    }
    cpa_commit();
  }

  float m_lo = -1e30f, m_hi = -1e30f, l_lo = 0.f, l_hi = 0.f;
  float oacc[16][4];
#pragma unroll
  for (int i = 0; i < 16; ++i)
#pragma unroll
    for (int j = 0; j < 4; ++j) oacc[i][j] = 0.f;

  const int a_row = lane & 15;
  const int a_col = (lane >> 4) * 8;
  const int b_row = (lane & 7) + ((lane & 16) >> 1);
  const int b_col = lane & 8;

  for (int t = 0; t <= mt; ++t) {
    const int n0 = t * 64;
    __syncthreads();                   // previous compute done
    {
      const int r = tid >> 4;
      const int cvec = (tid & 15) * 8;
#pragma unroll
      for (int it = 0; it < 8; ++it) {
        int row = r + it * 8;
        size_t gi = ((size_t)(b * SEQ + n0 + row) * NKV + g) * HD + cvec;
        uint32_t e = (uint32_t)(row * FSD + cvec) * 2;
        cpa16(sbase + KHO * 2 + e, kh + gi);
        cpa16(sbase + KLO * 2 + e, kl + gi);
        cpa16(sbase + VHO * 2 + e, vh + gi);
        cpa16(sbase + VLO * 2 + e, vl + gi);
      }
      cpa_commit();
    }
    cpa_wait0();
    __syncthreads();

    // --- S = Q @ (Kh + Kl*2^-10)^T ---
    float sacc[8][4];
#pragma unroll
    for (int i = 0; i < 8; ++i)
#pragma unroll
      for (int j = 0; j < 4; ++j) sacc[i][j] = 0.f;

#pragma unroll
    for (int kc = 0; kc < 8; ++kc) {
      uint32_t aq_off = (uint32_t)((w * 16 + a_row) * FSD + kc * 16 + a_col) * 2;
      uint32_t aq[4], aqs[4];
      ldsm_x4(sbase + QO * 2 + aq_off, aq);
#pragma unroll
      for (int qq = 0; qq < 4; ++qq) aqs[qq] = hscale(aq[qq]);
#pragma unroll
      for (int np = 0; np < 4; ++np) {
        uint32_t bo = (uint32_t)((np * 16 + b_row) * FSD + kc * 16 + b_col) * 2;
        uint32_t bh[4], bl[4];
        ldsm_x4(sbase + KHO * 2 + bo, bh);
        ldsm_x4(sbase + KLO * 2 + bo, bl);
        mma_f16(sacc[np * 2], aq, bh);
        mma_f16(sacc[np * 2], aqs, bl);
        mma_f16(sacc[np * 2 + 1], aq, bh + 2);
        mma_f16(sacc[np * 2 + 1], aqs, bl + 2);
      }
    }

    if (t == mt) {
      int row_lo = w * 16 + (lane >> 2);
      int row_hi = row_lo + 8;
#pragma unroll
      for (int nt = 0; nt < 8; ++nt) {
        int c0 = nt * 8 + (lane & 3) * 2;
        if (c0 > row_lo) sacc[nt][0] = -1e30f;
        if (c0 + 1 > row_lo) sacc[nt][1] = -1e30f;
        if (c0 > row_hi) sacc[nt][2] = -1e30f;
        if (c0 + 1 > row_hi) sacc[nt][3] = -1e30f;
      }
    }

    // --- online softmax ---
    float rmax_lo = -1e30f, rmax_hi = -1e30f;
#pragma unroll
    for (int nt = 0; nt < 8; ++nt) {
      rmax_lo = fmaxf(rmax_lo, fmaxf(sacc[nt][0], sacc[nt][1]));
      rmax_hi = fmaxf(rmax_hi, fmaxf(sacc[nt][2], sacc[nt][3]));
    }
#pragma unroll
    for (int d = 1; d < 4; d <<= 1) {
      rmax_lo = fmaxf(rmax_lo, __shfl_xor_sync(0xffffffffu, rmax_lo, d));
      rmax_hi = fmaxf(rmax_hi, __shfl_xor_sync(0xffffffffu, rmax_hi, d));
    }
    float mn_lo = fmaxf(m_lo, rmax_lo);
    float mn_hi = fmaxf(m_hi, rmax_hi);
    float f_lo = __expf(m_lo - mn_lo);
    float f_hi = __expf(m_hi - mn_hi);
    m_lo = mn_lo; m_hi = mn_hi;

    float rsum_lo = 0.f, rsum_hi = 0.f;
#pragma unroll
    for (int nt = 0; nt < 8; ++nt) {
      sacc[nt][0] = __expf(sacc[nt][0] - mn_lo);
      sacc[nt][1] = __expf(sacc[nt][1] - mn_lo);
      sacc[nt][2] = __expf(sacc[nt][2] - mn_hi);
      sacc[nt][3] = __expf(sacc[nt][3] - mn_hi);
      rsum_lo += sacc[nt][0] + sacc[nt][1];
      rsum_hi += sacc[nt][2] + sacc[nt][3];
    }
#pragma unroll
    for (int d = 1; d < 4; d <<= 1) {
      rsum_lo += __shfl_xor_sync(0xffffffffu, rsum_lo, d);
      rsum_hi += __shfl_xor_sync(0xffffffffu, rsum_hi, d);
    }
    l_lo = l_lo * f_lo + rsum_lo;
    l_hi = l_hi * f_hi + rsum_hi;
#pragma unroll
    for (int i = 0; i < 16; ++i) {
      oacc[i][0] *= f_lo; oacc[i][1] *= f_lo;
      oacc[i][2] *= f_hi; oacc[i][3] *= f_hi;
    }

    // --- O += P @ (Vh + Vl*2^-10) ---
#pragma unroll
    for (int kt = 0; kt < 4; ++kt) {
      const float* s0 = sacc[2 * kt];
      const float* s1 = sacc[2 * kt + 1];
      uint32_t ph[4], ps[4];
      ph[0] = pack_f16(s0[0], s0[1]);
      ph[1] = pack_f16(s0[2], s0[3]);
      ph[2] = pack_f16(s1[0], s1[1]);
      ph[3] = pack_f16(s1[2], s1[3]);
      ps[0] = pack_f16(s0[0] * INV_LO_SCALE, s0[1] * INV_LO_SCALE);
      ps[1] = pack_f16(s0[2] * INV_LO_SCALE, s0[3] * INV_LO_SCALE);
      ps[2] = pack_f16(s1[0] * INV_LO_SCALE, s1[1] * INV_LO_SCALE);
      ps[3] = pack_f16(s1[2] * INV_LO_SCALE, s1[3] * INV_LO_SCALE);
#pragma unroll
      for (int dp = 0; dp < 8; ++dp) {
        uint32_t vo = (uint32_t)((kt * 16 + (lane & 15)) * FSD + dp * 16 +
                                 ((lane >> 4) << 3)) * 2;
        uint32_t vhf[4], vlf[4];
        ldsm_x4_t(sbase + VHO * 2 + vo, vhf);
        ldsm_x4_t(sbase + VLO * 2 + vo, vlf);
        mma_f16(oacc[dp * 2], ph, vhf);
        mma_f16(oacc[dp * 2], ps, vlf);
        mma_f16(oacc[dp * 2 + 1], ph, vhf + 2);
        mma_f16(oacc[dp * 2 + 1], ps, vlf + 2);
      }
    }
  }

  // --- epilogue: normalize, round to fp16, write [b,s,h,d] ---
  float inv_lo = 1.f / l_lo;
  float inv_hi = 1.f / l_hi;
  int r_lo = m0 + w * 16 + (lane >> 2);
  int r_hi = r_lo + 8;
#pragma unroll
  for (int dt = 0; dt < 16; ++dt) {
    int col = dt * 8 + (lane & 3) * 2;
    size_t i0 = ((size_t)(b * SEQ + r_lo) * NH + h) * HD + col;
    size_t i1 = ((size_t)(b * SEQ + r_hi) * NH + h) * HD + col;
    *(uint32_t*)(ao + i0) = pack_f16(oacc[dt][0] * inv_lo, oacc[dt][1] * inv_lo);
    *(uint32_t*)(ao + i1) = pack_f16(oacc[dt][2] * inv_hi, oacc[dt][3] * inv_hi);
  }
}

// ---------------------------------------------------------------------------
// Launch
// ---------------------------------------------------------------------------
extern "C" void kernel_launch(void* const* d_in, const int* in_sizes, int n_in,
                              void* d_out, int out_size) {
  const float* x    = (const float*)d_in[0];
  const float* fcos = (const float*)d_in[1];
  const float* fsin = (const float*)d_in[2];
  // d_in[3] = mask (causal mask applied analytically)
  const float* wq = (const float*)d_in[4];
  const float* wk = (const float*)d_in[5];
  const float* wv = (const float*)d_in[6];
  const float* wo = (const float*)d_in[7];
  float* out = (float*)d_out;

  float *q, *k;
  cudaGetSymbolAddress((void**)&q, g_q);
  cudaGetSymbolAddress((void**)&k, g_k);
  __half *xh, *aoh, *qh, *kh, *kl, *vh, *vl;
  __half *wqkvh, *wqkvl, *woh, *wol;
  cudaGetSymbolAddress((void**)&xh, g_xh);
  cudaGetSymbolAddress((void**)&aoh, g_aoh);
  cudaGetSymbolAddress((void**)&qh, g_qh);
  cudaGetSymbolAddress((void**)&kh, g_kh);
  cudaGetSymbolAddress((void**)&kl, g_kl);
  cudaGetSymbolAddress((void**)&vh, g_vh);
  cudaGetSymbolAddress((void**)&vl, g_vl);
  cudaGetSymbolAddress((void**)&wqkvh, g_wqkv_h);
  cudaGetSymbolAddress((void**)&wqkvl, g_wqkv_l);
  cudaGetSymbolAddress((void**)&woh, g_wo_h);
  cudaGetSymbolAddress((void**)&wol, g_wo_l);

  static bool attr_done = false;
  if (!attr_done) {
    cudaFuncSetAttribute(gemm_mma_kernel<0>,
                         cudaFuncAttributeMaxDynamicSharedMemorySize, GEMM_SMEM);
    cudaFuncSetAttribute(gemm_mma_kernel<1>,
                         cudaFuncAttributeMaxDynamicSharedMemorySize, GEMM_SMEM);
    cudaFuncSetAttribute(fa_mma_kernel,
                         cudaFuncAttributeMaxDynamicSharedMemorySize, FA_SMEM);
    attr_done = true;
  }

  // round x / transpose+split weights into combined QKV + wo
  {
    int nx = MTOK * DMODEL;
    round_kernel<<<(nx + 255) / 256, 256>>>(x, xh, nx);
    dim3 blk(32, 8);
    transpose_split_kernel<<<dim3(DMODEL / 32, DMODEL / 32), blk>>>(
        wq, wqkvh, wqkvl, DMODEL, DMODEL);
    transpose_split_kernel<<<dim3(KVDIM / 32, DMODEL / 32), blk>>>(
        wk, wqkvh + (size_t)DMODEL * DMODEL, wqkvl + (size_t)DMODEL * DMODEL,
        DMODEL, KVDIM);
    transpose_split_kernel<<<dim3(KVDIM / 32, DMODEL / 32), blk>>>(
        wv, wqkvh + (size_t)(DMODEL + KVDIM) * DMODEL,
        wqkvl + (size_t)(DMODEL + KVDIM) * DMODEL, DMODEL, KVDIM);
    transpose_split_kernel<<<dim3(DMODEL / 32, DMODEL / 32), blk>>>(
        wo, woh, wol, DMODEL, DMODEL);
  }

  // fused QKV projection (one launch, 768 CTAs, R9 pipeline)
  gemm_mma_kernel<1><<<dim3(QKVN / 128, MTOK / 128), 256, GEMM_SMEM>>>(
      xh, wqkvh, wqkvl, nullptr, QKVN, DMODEL, q, k, vh, vl);

  // RoPE: Q single (pre-scaled), K split
  {
    const float scale = 0.08838834764831845f;  // 1/sqrt(128)
    int tq = BATCH * SEQ * NH * (HD / 2);
    rope_single_kernel<<<(tq + 255) / 256, 256>>>(q, fcos, fsin, qh, NH, scale);
    int tk = BATCH * SEQ * NKV * (HD / 2);
    rope_split_kernel<<<(tk + 255) / 256, 256>>>(k, fcos, fsin, kh, kl, NKV);
  }

  // Tensor-core flash attention (R9 structure)
  fa_mma_kernel<<<dim3(SEQ / 64, NH, BATCH), 128, FA_SMEM>>>(
      qh, kh, kl, vh, vl, aoh);

  // Output projection
  gemm_mma_kernel<0><<<dim3(DMODEL / 128, MTOK / 128), 256, GEMM_SMEM>>>(
      aoh, woh, wol, out, DMODEL, DMODEL, nullptr, nullptr, nullptr, nullptr);
}

// round 14
// speedup vs baseline: 1.5486x; 1.0072x over previous
#include <cuda_runtime.h>
#include <cuda_fp16.h>
#include <cstdint>
#include <math.h>

// Problem dims (fixed by reference)
#define BATCH 2
#define SEQ 2048
#define DMODEL 2048
#define NH 16
#define NKV 4
#define HD 128
#define MTOK (BATCH * SEQ)          // 4096 tokens
#define KVDIM (NKV * HD)            // 512
#define QKVN (DMODEL + 2 * KVDIM)   // 3072

// ---------------------------------------------------------------------------
// Scratch (device globals; runtime allocation is forbidden)
// ---------------------------------------------------------------------------
__device__ __half g_xh[MTOK * DMODEL];
__device__ __half g_aoh[MTOK * DMODEL];
__device__ __half g_qh[MTOK * NH * HD];
__device__ __half g_kh[MTOK * KVDIM];
__device__ __half g_kl[MTOK * KVDIM];
__device__ __half g_vh[MTOK * KVDIM];
__device__ __half g_vl[MTOK * KVDIM];
// combined QKV weights [3072, 2048] (rows: wq 0-2047, wk 2048-2559, wv 2560-3071)
__device__ __half g_wqkv_h[QKVN * DMODEL];
__device__ __half g_wqkv_l[QKVN * DMODEL];
__device__ __half g_wo_h[DMODEL * DMODEL];
__device__ __half g_wo_l[DMODEL * DMODEL];

#define LO_SCALE 1024.0f
#define INV_LO_SCALE 0.0009765625f
#define HSC2 0x14001400u                     // fp16x2 constant 2^-10
#define QSCALE 0.08838834764831845f         // 1/sqrt(128)

// ---------------------------------------------------------------------------
// helpers
// ---------------------------------------------------------------------------
__device__ __forceinline__ uint32_t smem_u32(const void* p) {
  uint32_t a;
  asm("{ .reg .u64 t; cvta.to.shared.u64 t, %1; cvt.u32.u64 %0, t; }"
      : "=r"(a) : "l"(p));
  return a;
}
__device__ __forceinline__ void cpa16(uint32_t s, const void* g) {
  asm volatile("cp.async.cg.shared.global [%0], [%1], 16;"
               :: "r"(s), "l"(g) : "memory");
}
__device__ __forceinline__ void cpa_commit() {
  asm volatile("cp.async.commit_group;" ::: "memory");
}
__device__ __forceinline__ void cpa_wait0() {
  asm volatile("cp.async.wait_group 0;" ::: "memory");
}
__device__ __forceinline__ void ldsm_x4(uint32_t addr, uint32_t* r) {
  asm volatile("ldmatrix.sync.aligned.m8n8.x4.shared.b16 {%0,%1,%2,%3}, [%4];"
               : "=r"(r[0]), "=r"(r[1]), "=r"(r[2]), "=r"(r[3]) : "r"(addr));
}
__device__ __forceinline__ void ldsm_x4_t(uint32_t addr, uint32_t* r) {
  asm volatile("ldmatrix.sync.aligned.m8n8.x4.trans.shared.b16 {%0,%1,%2,%3}, [%4];"
               : "=r"(r[0]), "=r"(r[1]), "=r"(r[2]), "=r"(r[3]) : "r"(addr));
}
__device__ __forceinline__ void mma_f16(float* d, const uint32_t* a,
                                        const uint32_t* b) {
  asm volatile(
      "mma.sync.aligned.m16n8k16.row.col.f32.f16.f16.f32 "
      "{%0,%1,%2,%3}, {%4,%5,%6,%7}, {%8,%9}, {%0,%1,%2,%3};"
      : "+f"(d[0]), "+f"(d[1]), "+f"(d[2]), "+f"(d[3])
      : "r"(a[0]), "r"(a[1]), "r"(a[2]), "r"(a[3]), "r"(b[0]), "r"(b[1]));
}
__device__ __forceinline__ uint32_t pack_f16(float a, float b) {
  uint32_t r;
  asm("cvt.rn.f16x2.f32 %0, %1, %2;" : "=r"(r) : "f"(b), "f"(a));
  return r;
}
__device__ __forceinline__ float f16_round(float f) {
  return __half2float(__float2half(f));
}
__device__ __forceinline__ uint32_t hscale(uint32_t x) {
  uint32_t r;
  asm("mul.f16x2 %0, %1, %2;" : "=r"(r) : "r"(x), "r"(HSC2));
  return r;
}

// ---------------------------------------------------------------------------
// Conversion kernels
// ---------------------------------------------------------------------------
__global__ void round_kernel(const float* __restrict__ src,
                             __half* __restrict__ dst, int n) {
  int i = blockIdx.x * blockDim.x + threadIdx.x;
  if (i >= n) return;
  dst[i] = __float2half(src[i]);
}

__global__ void transpose_split_kernel(const float* __restrict__ w,
                                       __half* __restrict__ th,
                                       __half* __restrict__ tl,
                                       int K, int N) {
  __shared__ float tile[32][33];
  int nx = blockIdx.x * 32 + threadIdx.x;
  int k0 = blockIdx.y * 32;
  for (int i = threadIdx.y; i < 32; i += 8)
    tile[i][threadIdx.x] = w[(size_t)(k0 + i) * N + nx];
  __syncthreads();
  for (int j = threadIdx.y; j < 32; j += 8) {
    int n = blockIdx.x * 32 + j;
    int kk = k0 + threadIdx.x;
    float f = tile[threadIdx.x][j];
    float h = f16_round(f);
    th[(size_t)n * K + kk] = __float2half(h);
    tl[(size_t)n * K + kk] = __float2half((f - h) * LO_SCALE);
  }
}

// ---------------------------------------------------------------------------
// mma.sync fp16 2-product GEMM, 2-stage cp.async pipeline.
// MODE 0: plain fp32 C[M,N].
// MODE 1: fused QKV epilogue with in-register RoPE:
//   Q cols -> rope+scale -> qh fp16; K cols -> rope -> kh/kl split;
//   V cols -> vh/vl split.
// 128x128 CTA tile, BK=32, 256 thr, 8 warps (warp tile 32x64).
// ---------------------------------------------------------------------------
#define SB 40
#define T2E (128 * SB)
#define STG_E (3 * T2E)
#define GEMM_SMEM (2 * STG_E * 2)      // 61440 B

template <int MODE>
__global__ __launch_bounds__(256, 2) void gemm_mma_kernel(
    const __half* __restrict__ A, const __half* __restrict__ Bh,
    const __half* __restrict__ Bl, float* __restrict__ C, int N, int K,
    const float* __restrict__ fcos, const float* __restrict__ fsin,
    __half* __restrict__ Qh, __half* __restrict__ Kh, __half* __restrict__ Kl,
    __half* __restrict__ Vh, __half* __restrict__ Vl) {
  extern __shared__ __half smb[];
  const int tid = threadIdx.x;
  const int lane = tid & 31;
  const int wid = tid >> 5;
  const int wm = wid & 3;
  const int wn = wid >> 2;
  const int m0 = blockIdx.y * 128;
  const int n0 = blockIdx.x * 128;
  const uint32_t sbase = smem_u32(smb);

  const uint32_t OA = 0, OBH = T2E, OBL = 2 * T2E;

  float acc[2][8][4];
#pragma unroll
  for (int i = 0; i < 2; ++i)
#pragma unroll
    for (int j = 0; j < 8; ++j)
#pragma unroll
      for (int q = 0; q < 4; ++q) acc[i][j][q] = 0.f;

  const int a_row = lane & 15;
  const int a_col = (lane >> 4) * 8;
  const int b_row = (lane & 7) + ((lane & 16) >> 1);
  const int b_col = lane & 8;

  const int l_r = tid >> 2;
  const int l_c = (tid & 3) * 8;

  const int nchunks = K >> 5;

  {
#pragma unroll
    for (int it = 0; it < 2; ++it) {
      int r = l_r + it * 64;
      const size_t ga = (size_t)(m0 + r) * K + l_c;
      const size_t gb = (size_t)(n0 + r) * K + l_c;
      uint32_t so = (uint32_t)(r * SB + l_c) * 2;
      cpa16(sbase + OA * 2 + so, A + ga);
      cpa16(sbase + OBH * 2 + so, Bh + gb);
      cpa16(sbase + OBL * 2 + so, Bl + gb);
    }
    cpa_commit();
  }

  for (int c = 0; c < nchunks; ++c) {
    cpa_wait0();
    __syncthreads();
    if (c + 1 < nchunks) {
      const int k0g = (c + 1) << 5;
      const uint32_t stb = sbase + ((c + 1) & 1) * (STG_E * 2);
#pragma unroll
      for (int it = 0; it < 2; ++it) {
        int r = l_r + it * 64;
        const size_t ga = (size_t)(m0 + r) * K + k0g + l_c;
        const size_t gb = (size_t)(n0 + r) * K + k0g + l_c;
        uint32_t so = (uint32_t)(r * SB + l_c) * 2;
        cpa16(stb + OA * 2 + so, A + ga);
        cpa16(stb + OBH * 2 + so, Bh + gb);
        cpa16(stb + OBL * 2 + so, Bl + gb);
      }
      cpa_commit();
    }

    const uint32_t stg = sbase + (c & 1) * (STG_E * 2);
#pragma unroll
    for (int s = 0; s < 2; ++s) {
      const int k0 = s * 16;
      uint32_t af[2][4], afs[2][4];
#pragma unroll
      for (int mt = 0; mt < 2; ++mt) {
        uint32_t off = (uint32_t)((wm * 32 + mt * 16 + a_row) * SB + k0 + a_col) * 2;
        ldsm_x4(stg + OA * 2 + off, af[mt]);
#pragma unroll
        for (int qq = 0; qq < 4; ++qq) afs[mt][qq] = hscale(af[mt][qq]);
      }
#pragma unroll
      for (int nt2 = 0; nt2 < 4; ++nt2) {
        uint32_t bh[4], bl[4];
        uint32_t off = (uint32_t)((wn * 64 + nt2 * 16 + b_row) * SB + k0 + b_col) * 2;
        ldsm_x4(stg + OBH * 2 + off, bh);
        ldsm_x4(stg + OBL * 2 + off, bl);
#pragma unroll
        for (int mt = 0; mt < 2; ++mt) {
          mma_f16(acc[mt][nt2 * 2], af[mt], bh);
          mma_f16(acc[mt][nt2 * 2], afs[mt], bl);
          mma_f16(acc[mt][nt2 * 2 + 1], af[mt], bh + 2);
          mma_f16(acc[mt][nt2 * 2 + 1], afs[mt], bl + 2);
        }
      }
    }
  }

#pragma unroll
  for (int mt = 0; mt < 2; ++mt) {
    int r0 = m0 + wm * 32 + mt * 16 + (lane >> 2);
#pragma unroll
    for (int nt = 0; nt < 8; ++nt) {
      int col = n0 + wn * 64 + nt * 8 + (lane & 3) * 2;
      float a0 = acc[mt][nt][0], a1 = acc[mt][nt][1];
      float b0 = acc[mt][nt][2], b1 = acc[mt][nt][3];
      if (MODE == 0) {
        float2 v0 = {a0, a1};
        float2 v1 = {b0, b1};
        *(float2*)(C + (size_t)r0 * N + col) = v0;
        *(float2*)(C + (size_t)(r0 + 8) * N + col) = v1;
      } else {
        int r1 = r0 + 8;
        if (col < DMODEL) {                    // Q: rope + scale -> fp16
          int p = (col & (HD - 1)) >> 1;       // pair index within head
          int s0r = r0 & (SEQ - 1);
          int s1r = r1 & (SEQ - 1);
          float c0 = fcos[s0r * 64 + p], sn0 = fsin[s0r * 64 + p];
          float c1 = fcos[s1r * 64 + p], sn1 = fsin[s1r * 64 + p];
          float q0 = (a0 * c0 - a1 * sn0) * QSCALE;
          float q1 = (a0 * sn0 + a1 * c0) * QSCALE;
          float q2 = (b0 * c1 - b1 * sn1) * QSCALE;
          float q3 = (b0 * sn1 + b1 * c1) * QSCALE;
          *(uint32_t*)(Qh + (size_t)r0 * DMODEL + col) = pack_f16(q0, q1);
          *(uint32_t*)(Qh + (size_t)r1 * DMODEL + col) = pack_f16(q2, q3);
        } else if (col < DMODEL + KVDIM) {     // K: rope -> split fp16
          int kc = col - DMODEL;
          int p = (kc & (HD - 1)) >> 1;
          int s0r = r0 & (SEQ - 1);
          int s1r = r1 & (SEQ - 1);
          float c0 = fcos[s0r * 64 + p], sn0 = fsin[s0r * 64 + p];
          float c1 = fcos[s1r * 64 + p], sn1 = fsin[s1r * 64 + p];
          float k0v = a0 * c0 - a1 * sn0;
          float k1v = a0 * sn0 + a1 * c0;
          float k2v = b0 * c1 - b1 * sn1;
          float k3v = b0 * sn1 + b1 * c1;
          *(uint32_t*)(Kh + (size_t)r0 * KVDIM + kc) = pack_f16(k0v, k1v);
          *(uint32_t*)(Kl + (size_t)r0 * KVDIM + kc) =
              pack_f16((k0v - f16_round(k0v)) * LO_SCALE,
                       (k1v - f16_round(k1v)) * LO_SCALE);
          *(uint32_t*)(Kh + (size_t)r1 * KVDIM + kc) = pack_f16(k2v, k3v);
          *(uint32_t*)(Kl + (size_t)r1 * KVDIM + kc) =
              pack_f16((k2v - f16_round(k2v)) * LO_SCALE,
                       (k3v - f16_round(k3v)) * LO_SCALE);
        } else {                               // V: split fp16
          int vc = col - DMODEL - KVDIM;
          *(uint32_t*)(Vh + (size_t)r0 * KVDIM + vc) = pack_f16(a0, a1);
          *(uint32_t*)(Vl + (size_t)r0 * KVDIM + vc) =
              pack_f16((a0 - f16_round(a0)) * LO_SCALE,
                       (a1 - f16_round(a1)) * LO_SCALE);
          *(uint32_t*)(Vh + (size_t)r1 * KVDIM + vc) = pack_f16(b0, b1);
          *(uint32_t*)(Vl + (size_t)r1 * KVDIM + vc) =
              pack_f16((b0 - f16_round(b0)) * LO_SCALE,
                       (b1 - f16_round(b1)) * LO_SCALE);
        }
      }
    }
  }
}

// ---------------------------------------------------------------------------
// Tensor-core flash attention, fp16 2-product, causal (R9/R12 structure).
// BLOCK_M=64 (4 warps x m16), BLOCK_N=64, D=128. 87 KB smem -> 2 CTAs/SM.
// ---------------------------------------------------------------------------
#define FSD 136                       // smem stride (elements)
#define FTE (64 * FSD)                // elements per tile
#define FA_SMEM (5 * FTE * 2)         // Q,Kh,Kl,Vh,Vl = 87040 B

__global__ __launch_bounds__(128) void fa_mma_kernel(
    const __half* __restrict__ qh, const __half* __restrict__ kh,
    const __half* __restrict__ kl, const __half* __restrict__ vh,
    const __half* __restrict__ vl, __half* __restrict__ ao) {
  extern __shared__ __half fsm[];
  const uint32_t sbase = smem_u32(fsm);
  const int tid = threadIdx.x;
  const int lane = tid & 31;
  const int w = tid >> 5;

  const int mt = gridDim.x - 1 - blockIdx.x;   // heavy tiles first
  const int m0 = mt * 64;
  const int h = blockIdx.y;
  const int b = blockIdx.z;
  const int g = h >> 2;

  const uint32_t QO = 0, KHO = FTE, KLO = 2 * FTE, VHO = 3 * FTE,
                 VLO = 4 * FTE;

  // --- async-load Q tile (pre-scaled fp16) ---
  {
    const int r = tid >> 4;
    const int cvec = (tid & 15) * 8;
#pragma unroll
    for (int it = 0; it < 8; ++it) {
      int row = r + it * 8;
      size_t gi = ((size_t)(b * SEQ + m0 + row) * NH + h) * HD + cvec;
      cpa16(sbase + (QO + (uint32_t)(row * FSD + cvec)) * 2, qh + gi);
    }
    cpa_commit();
  }

  float m_lo = -1e30f, m_hi = -1e30f, l_lo = 0.f, l_hi = 0.f;
  float oacc[16][4];
#pragma unroll
  for (int i = 0; i < 16; ++i)
#pragma unroll
    for (int j = 0; j < 4; ++j) oacc[i][j] = 0.f;

  const int a_row = lane & 15;
  const int a_col = (lane >> 4) * 8;
  const int b_row = (lane & 7) + ((lane & 16) >> 1);
  const int b_col = lane & 8;

  for (int t = 0; t <= mt; ++t) {
    const int n0 = t * 64;
    __syncthreads();                   // previous compute done
    {
      const int r = tid >> 4;
      const int cvec = (tid & 15) * 8;
#pragma unroll
      for (int it = 0; it < 8; ++it) {
        int row = r + it * 8;
        size_t gi = ((size_t)(b * SEQ + n0 + row) * NKV + g) * HD + cvec;
        uint32_t e = (uint32_t)(row * FSD + cvec) * 2;
        cpa16(sbase + KHO * 2 + e, kh + gi);
        cpa16(sbase + KLO * 2 + e, kl + gi);
        cpa16(sbase + VHO * 2 + e, vh + gi);
        cpa16(sbase + VLO * 2 + e, vl + gi);
      }
      cpa_commit();
    }
    cpa_wait0();
    __syncthreads();

    // --- S = Q @ (Kh + Kl*2^-10)^T ---
    float sacc[8][4];
#pragma unroll
    for (int i = 0; i < 8; ++i)
#pragma unroll
      for (int j = 0; j < 4; ++j) sacc[i][j] = 0.f;

#pragma unroll
    for (int kc = 0; kc < 8; ++kc) {
      uint32_t aq_off = (uint32_t)((w * 16 + a_row) * FSD + kc * 16 + a_col) * 2;
      uint32_t aq[4], aqs[4];
      ldsm_x4(sbase + QO * 2 + aq_off, aq);
#pragma unroll
      for (int qq = 0; qq < 4; ++qq) aqs[qq] = hscale(aq[qq]);
#pragma unroll
      for (int np = 0; np < 4; ++np) {
        uint32_t bo = (uint32_t)((np * 16 + b_row) * FSD + kc * 16 + b_col) * 2;
        uint32_t bh[4], bl[4];
        ldsm_x4(sbase + KHO * 2 + bo, bh);
        ldsm_x4(sbase + KLO * 2 + bo, bl);
        mma_f16(sacc[np * 2], aq, bh);
        mma_f16(sacc[np * 2], aqs, bl);
        mma_f16(sacc[np * 2 + 1], aq, bh + 2);
        mma_f16(sacc[np * 2 + 1], aqs, bl + 2);
      }
    }

    if (t == mt) {
      int row_lo = w * 16 + (lane >> 2);
      int row_hi = row_lo + 8;
#pragma unroll
      for (int nt = 0; nt < 8; ++nt) {
        int c0 = nt * 8 + (lane & 3) * 2;
        if (c0 > row_lo) sacc[nt][0] = -1e30f;
        if (c0 + 1 > row_lo) sacc[nt][1] = -1e30f;
        if (c0 > row_hi) sacc[nt][2] = -1e30f;
        if (c0 + 1 > row_hi) sacc[nt][3] = -1e30f;
      }
    }

    // --- online softmax ---
    float rmax_lo = -1e30f, rmax_hi = -1e30f;
#pragma unroll
    for (int nt = 0; nt < 8; ++nt) {
      rmax_lo = fmaxf(rmax_lo, fmaxf(sacc[nt][0], sacc[nt][1]));
      rmax_hi = fmaxf(rmax_hi, fmaxf(sacc[nt][2], sacc[nt][3]));
    }
#pragma unroll
    for (int d = 1; d < 4; d <<= 1) {
      rmax_lo = fmaxf(rmax_lo, __shfl_xor_sync(0xffffffffu, rmax_lo, d));
      rmax_hi = fmaxf(rmax_hi, __shfl_xor_sync(0xffffffffu, rmax_hi, d));
    }
    float mn_lo = fmaxf(m_lo, rmax_lo);
    float mn_hi = fmaxf(m_hi, rmax_hi);
    float f_lo = __expf(m_lo - mn_lo);
    float f_hi = __expf(m_hi - mn_hi);
    m_lo = mn_lo; m_hi = mn_hi;

    float rsum_lo = 0.f, rsum_hi = 0.f;
#pragma unroll
    for (int nt = 0; nt < 8; ++nt) {
      sacc[nt][0] = __expf(sacc[nt][0] - mn_lo);
      sacc[nt][1] = __expf(sacc[nt][1] - mn_lo);
      sacc[nt][2] = __expf(sacc[nt][2] - mn_hi);
      sacc[nt][3] = __expf(sacc[nt][3] - mn_hi);
      rsum_lo += sacc[nt][0] + sacc[nt][1];
      rsum_hi += sacc[nt][2] + sacc[nt][3];
    }
#pragma unroll
    for (int d = 1; d < 4; d <<= 1) {
      rsum_lo += __shfl_xor_sync(0xffffffffu, rsum_lo, d);
      rsum_hi += __shfl_xor_sync(0xffffffffu, rsum_hi, d);
    }
    l_lo = l_lo * f_lo + rsum_lo;
    l_hi = l_hi * f_hi + rsum_hi;
#pragma unroll
    for (int i = 0; i < 16; ++i) {
      oacc[i][0] *= f_lo; oacc[i][1] *= f_lo;
      oacc[i][2] *= f_hi; oacc[i][3] *= f_hi;
    }

    // --- O += P @ (Vh + Vl*2^-10) ---
#pragma unroll
    for (int kt = 0; kt < 4; ++kt) {
      const float* s0 = sacc[2 * kt];
      const float* s1 = sacc[2 * kt + 1];
      uint32_t ph[4], ps[4];
      ph[0] = pack_f16(s0[0], s0[1]);
      ph[1] = pack_f16(s0[2], s0[3]);
      ph[2] = pack_f16(s1[0], s1[1]);
      ph[3] = pack_f16(s1[2], s1[3]);
      ps[0] = pack_f16(s0[0] * INV_LO_SCALE, s0[1] * INV_LO_SCALE);
      ps[1] = pack_f16(s0[2] * INV_LO_SCALE, s0[3] * INV_LO_SCALE);
      ps[2] = pack_f16(s1[0] * INV_LO_SCALE, s1[1] * INV_LO_SCALE);
      ps[3] = pack_f16(s1[2] * INV_LO_SCALE, s1[3] * INV_LO_SCALE);
#pragma unroll
      for (int dp = 0; dp < 8; ++dp) {
        uint32_t vo = (uint32_t)((kt * 16 + (lane & 15)) * FSD + dp * 16 +
                                 ((lane >> 4) << 3)) * 2;
        uint32_t vhf[4], vlf[4];
        ldsm_x4_t(sbase + VHO * 2 + vo, vhf);
        ldsm_x4_t(sbase + VLO * 2 + vo, vlf);
        mma_f16(oacc[dp * 2], ph, vhf);
        mma_f16(oacc[dp * 2], ps, vlf);
        mma_f16(oacc[dp * 2 + 1], ph, vhf + 2);
        mma_f16(oacc[dp * 2 + 1], ps, vlf + 2);
      }
    }
  }

  // --- epilogue: normalize, round to fp16, write [b,s,h,d] ---
  float inv_lo = 1.f / l_lo;
  float inv_hi = 1.f / l_hi;
  int r_lo = m0 + w * 16 + (lane >> 2);
  int r_hi = r_lo + 8;
#pragma unroll
  for (int dt = 0; dt < 16; ++dt) {
    int col = dt * 8 + (lane & 3) * 2;
    size_t i0 = ((size_t)(b * SEQ + r_lo) * NH + h) * HD + col;
    size_t i1 = ((size_t)(b * SEQ + r_hi) * NH + h) * HD + col;
    *(uint32_t*)(ao + i0) = pack_f16(oacc[dt][0] * inv_lo, oacc[dt][1] * inv_lo);
    *(uint32_t*)(ao + i1) = pack_f16(oacc[dt][2] * inv_hi, oacc[dt][3] * inv_hi);
  }
}

// ---------------------------------------------------------------------------
// Launch
// ---------------------------------------------------------------------------
extern "C" void kernel_launch(void* const* d_in, const int* in_sizes, int n_in,
                              void* d_out, int out_size) {
  const float* x    = (const float*)d_in[0];
  const float* fcos = (const float*)d_in[1];
  const float* fsin = (const float*)d_in[2];
  // d_in[3] = mask (causal mask applied analytically)
  const float* wq = (const float*)d_in[4];
  const float* wk = (const float*)d_in[5];
  const float* wv = (const float*)d_in[6];
  const float* wo = (const float*)d_in[7];
  float* out = (float*)d_out;

  __half *xh, *aoh, *qh, *kh, *kl, *vh, *vl;
  __half *wqkvh, *wqkvl, *woh, *wol;
  cudaGetSymbolAddress((void**)&xh, g_xh);
  cudaGetSymbolAddress((void**)&aoh, g_aoh);
  cudaGetSymbolAddress((void**)&qh, g_qh);
  cudaGetSymbolAddress((void**)&kh, g_kh);
  cudaGetSymbolAddress((void**)&kl, g_kl);
  cudaGetSymbolAddress((void**)&vh, g_vh);
  cudaGetSymbolAddress((void**)&vl, g_vl);
  cudaGetSymbolAddress((void**)&wqkvh, g_wqkv_h);
  cudaGetSymbolAddress((void**)&wqkvl, g_wqkv_l);
  cudaGetSymbolAddress((void**)&woh, g_wo_h);
  cudaGetSymbolAddress((void**)&wol, g_wo_l);

  static bool attr_done = false;
  if (!attr_done) {
    cudaFuncSetAttribute(gemm_mma_kernel<0>,
                         cudaFuncAttributeMaxDynamicSharedMemorySize, GEMM_SMEM);
    cudaFuncSetAttribute(gemm_mma_kernel<1>,
                         cudaFuncAttributeMaxDynamicSharedMemorySize, GEMM_SMEM);
    cudaFuncSetAttribute(fa_mma_kernel,
                         cudaFuncAttributeMaxDynamicSharedMemorySize, FA_SMEM);
    attr_done = true;
  }

  // round x / transpose+split weights into combined QKV + wo
  {
    int nx = MTOK * DMODEL;
    round_kernel<<<(nx + 255) / 256, 256>>>(x, xh, nx);
    dim3 blk(32, 8);
    transpose_split_kernel<<<dim3(DMODEL / 32, DMODEL / 32), blk>>>(
        wq, wqkvh, wqkvl, DMODEL, DMODEL);
    transpose_split_kernel<<<dim3(KVDIM / 32, DMODEL / 32), blk>>>(
        wk, wqkvh + (size_t)DMODEL * DMODEL, wqkvl + (size_t)DMODEL * DMODEL,
        DMODEL, KVDIM);
    transpose_split_kernel<<<dim3(KVDIM / 32, DMODEL / 32), blk>>>(
        wv, wqkvh + (size_t)(DMODEL + KVDIM) * DMODEL,
        wqkvl + (size_t)(DMODEL + KVDIM) * DMODEL, DMODEL, KVDIM);
    transpose_split_kernel<<<dim3(DMODEL / 32, DMODEL / 32), blk>>>(
        wo, woh, wol, DMODEL, DMODEL);
  }

  // fused QKV projection + in-register RoPE (one launch, 768 CTAs)
  gemm_mma_kernel<1><<<dim3(QKVN / 128, MTOK / 128), 256, GEMM_SMEM>>>(
      xh, wqkvh, wqkvl, nullptr, QKVN, DMODEL, fcos, fsin,
      qh, kh, kl, vh, vl);

  // Tensor-core flash attention
  fa_mma_kernel<<<dim3(SEQ / 64, NH, BATCH), 128, FA_SMEM>>>(
      qh, kh, kl, vh, vl, aoh);

  // Output projection
  gemm_mma_kernel<0><<<dim3(DMODEL / 128, MTOK / 128), 256, GEMM_SMEM>>>(
      aoh, woh, wol, out, DMODEL, DMODEL, nullptr, nullptr,
      nullptr, nullptr, nullptr, nullptr, nullptr);
}

// round 15
// speedup vs baseline: 1.6202x; 1.0462x over previous
#include <cuda_runtime.h>
#include <cuda_fp16.h>
#include <cstdint>
#include <math.h>

// Problem dims (fixed by reference)
#define BATCH 2
#define SEQ 2048
#define DMODEL 2048
#define NH 16
#define NKV 4
#define HD 128
#define MTOK (BATCH * SEQ)          // 4096 tokens
#define KVDIM (NKV * HD)            // 512
#define QKVN (DMODEL + 2 * KVDIM)   // 3072

// ---------------------------------------------------------------------------
// Scratch (device globals; runtime allocation is forbidden)
// ---------------------------------------------------------------------------
__device__ __half g_xh[MTOK * DMODEL];
__device__ __half g_aoh[MTOK * DMODEL];
__device__ __half g_qh[MTOK * NH * HD];
__device__ __half g_kh[MTOK * KVDIM];
__device__ __half g_kl[MTOK * KVDIM];
__device__ __half g_vh[MTOK * KVDIM];
__device__ __half g_vl[MTOK * KVDIM];
// combined QKV weights [3072, 2048] (rows: wq 0-2047, wk 2048-2559, wv 2560-3071)
__device__ __half g_wqkv_h[QKVN * DMODEL];
__device__ __half g_wqkv_l[QKVN * DMODEL];
__device__ __half g_wo_h[DMODEL * DMODEL];
__device__ __half g_wo_l[DMODEL * DMODEL];

#define LO_SCALE 1024.0f
#define INV_LO_SCALE 0.0009765625f
#define HSC2 0x14001400u                     // fp16x2 constant 2^-10
#define QSCALE 0.08838834764831845f         // 1/sqrt(128)

// ---------------------------------------------------------------------------
// helpers
// ---------------------------------------------------------------------------
__device__ __forceinline__ uint32_t smem_u32(const void* p) {
  uint32_t a;
  asm("{ .reg .u64 t; cvta.to.shared.u64 t, %1; cvt.u32.u64 %0, t; }"
      : "=r"(a) : "l"(p));
  return a;
}
__device__ __forceinline__ void cpa16(uint32_t s, const void* g) {
  asm volatile("cp.async.cg.shared.global [%0], [%1], 16;"
               :: "r"(s), "l"(g) : "memory");
}
__device__ __forceinline__ void cpa_commit() {
  asm volatile("cp.async.commit_group;" ::: "memory");
}
__device__ __forceinline__ void cpa_wait0() {
  asm volatile("cp.async.wait_group 0;" ::: "memory");
}
__device__ __forceinline__ void ldsm_x4(uint32_t addr, uint32_t* r) {
  asm volatile("ldmatrix.sync.aligned.m8n8.x4.shared.b16 {%0,%1,%2,%3}, [%4];"
               : "=r"(r[0]), "=r"(r[1]), "=r"(r[2]), "=r"(r[3]) : "r"(addr));
}
__device__ __forceinline__ void ldsm_x4_t(uint32_t addr, uint32_t* r) {
  asm volatile("ldmatrix.sync.aligned.m8n8.x4.trans.shared.b16 {%0,%1,%2,%3}, [%4];"
               : "=r"(r[0]), "=r"(r[1]), "=r"(r[2]), "=r"(r[3]) : "r"(addr));
}
__device__ __forceinline__ void mma_f16(float* d, const uint32_t* a,
                                        const uint32_t* b) {
  asm volatile(
      "mma.sync.aligned.m16n8k16.row.col.f32.f16.f16.f32 "
      "{%0,%1,%2,%3}, {%4,%5,%6,%7}, {%8,%9}, {%0,%1,%2,%3};"
      : "+f"(d[0]), "+f"(d[1]), "+f"(d[2]), "+f"(d[3])
      : "r"(a[0]), "r"(a[1]), "r"(a[2]), "r"(a[3]), "r"(b[0]), "r"(b[1]));
}
__device__ __forceinline__ uint32_t pack_f16(float a, float b) {
  uint32_t r;
  asm("cvt.rn.f16x2.f32 %0, %1, %2;" : "=r"(r) : "f"(b), "f"(a));
  return r;
}
__device__ __forceinline__ float f16_round(float f) {
  return __half2float(__float2half(f));
}
__device__ __forceinline__ uint32_t hscale(uint32_t x) {
  uint32_t r;
  asm("mul.f16x2 %0, %1, %2;" : "=r"(r) : "r"(x), "r"(HSC2));
  return r;
}

// ---------------------------------------------------------------------------
// Conversion kernels
// ---------------------------------------------------------------------------
__global__ void round_kernel(const float* __restrict__ src,
                             __half* __restrict__ dst, int n) {
  int i = blockIdx.x * blockDim.x + threadIdx.x;
  if (i >= n) return;
  dst[i] = __float2half(src[i]);
}

__global__ void transpose_split_kernel(const float* __restrict__ w,
                                       __half* __restrict__ th,
                                       __half* __restrict__ tl,
                                       int K, int N) {
  __shared__ float tile[32][33];
  int nx = blockIdx.x * 32 + threadIdx.x;
  int k0 = blockIdx.y * 32;
  for (int i = threadIdx.y; i < 32; i += 8)
    tile[i][threadIdx.x] = w[(size_t)(k0 + i) * N + nx];
  __syncthreads();
  for (int j = threadIdx.y; j < 32; j += 8) {
    int n = blockIdx.x * 32 + j;
    int kk = k0 + threadIdx.x;
    float f = tile[threadIdx.x][j];
    float h = f16_round(f);
    th[(size_t)n * K + kk] = __float2half(h);
    tl[(size_t)n * K + kk] = __float2half((f - h) * LO_SCALE);
  }
}

// ---------------------------------------------------------------------------
// mma.sync fp16 2-product GEMM, 2-stage cp.async pipeline, BK=64.
// MODE 0: plain fp32 C[M,N].
// MODE 1: fused QKV epilogue with in-register RoPE.
// 128x128 CTA tile, 256 thr, 8 warps (warp tile 32x64).
// ---------------------------------------------------------------------------
#define SB 72                          // smem row stride (elements), BK=64+8 pad
#define T2E (128 * SB)                 // elements per tile
#define STG_E (3 * T2E)                // A, Bh, Bl per stage
#define GEMM_SMEM (2 * STG_E * 2)      // 110592 B

template <int MODE>
__global__ __launch_bounds__(256, 2) void gemm_mma_kernel(
    const __half* __restrict__ A, const __half* __restrict__ Bh,
    const __half* __restrict__ Bl, float* __restrict__ C, int N, int K,
    const float* __restrict__ fcos, const float* __restrict__ fsin,
    __half* __restrict__ Qh, __half* __restrict__ Kh, __half* __restrict__ Kl,
    __half* __restrict__ Vh, __half* __restrict__ Vl) {
  extern __shared__ __half smb[];
  const int tid = threadIdx.x;
  const int lane = tid & 31;
  const int wid = tid >> 5;
  const int wm = wid & 3;
  const int wn = wid >> 2;
  const int m0 = blockIdx.y * 128;
  const int n0 = blockIdx.x * 128;
  const uint32_t sbase = smem_u32(smb);

  const uint32_t OA = 0, OBH = T2E, OBL = 2 * T2E;

  float acc[2][8][4];
#pragma unroll
  for (int i = 0; i < 2; ++i)
#pragma unroll
    for (int j = 0; j < 8; ++j)
#pragma unroll
      for (int q = 0; q < 4; ++q) acc[i][j][q] = 0.f;

  const int a_row = lane & 15;
  const int a_col = (lane >> 4) * 8;
  const int b_row = (lane & 7) + ((lane & 16) >> 1);
  const int b_col = lane & 8;

  const int nchunks = K >> 6;          // K/64

  // load map: tile = 128 rows x 8 vectors(16B) = 1024 vectors; 4 per thread
  {
#pragma unroll
    for (int it = 0; it < 4; ++it) {
      int v = tid + it * 256;
      int r = v >> 3;
      int cv = (v & 7) * 8;
      const size_t ga = (size_t)(m0 + r) * K + cv;
      const size_t gb = (size_t)(n0 + r) * K + cv;
      uint32_t so = (uint32_t)(r * SB + cv) * 2;
      cpa16(sbase + OA * 2 + so, A + ga);
      cpa16(sbase + OBH * 2 + so, Bh + gb);
      cpa16(sbase + OBL * 2 + so, Bl + gb);
    }
    cpa_commit();
  }

  for (int c = 0; c < nchunks; ++c) {
    cpa_wait0();
    __syncthreads();
    if (c + 1 < nchunks) {
      const int k0g = (c + 1) << 6;
      const uint32_t stb = sbase + ((c + 1) & 1) * (STG_E * 2);
#pragma unroll
      for (int it = 0; it < 4; ++it) {
        int v = tid + it * 256;
        int r = v >> 3;
        int cv = (v & 7) * 8;
        const size_t ga = (size_t)(m0 + r) * K + k0g + cv;
        const size_t gb = (size_t)(n0 + r) * K + k0g + cv;
        uint32_t so = (uint32_t)(r * SB + cv) * 2;
        cpa16(stb + OA * 2 + so, A + ga);
        cpa16(stb + OBH * 2 + so, Bh + gb);
        cpa16(stb + OBL * 2 + so, Bl + gb);
      }
      cpa_commit();
    }

    const uint32_t stg = sbase + (c & 1) * (STG_E * 2);
#pragma unroll
    for (int s = 0; s < 4; ++s) {      // 4 k-steps of 16
      const int k0 = s * 16;
      uint32_t af[2][4], afs[2][4];
#pragma unroll
      for (int mt = 0; mt < 2; ++mt) {
        uint32_t off = (uint32_t)((wm * 32 + mt * 16 + a_row) * SB + k0 + a_col) * 2;
        ldsm_x4(stg + OA * 2 + off, af[mt]);
#pragma unroll
        for (int qq = 0; qq < 4; ++qq) afs[mt][qq] = hscale(af[mt][qq]);
      }
#pragma unroll
      for (int nt2 = 0; nt2 < 4; ++nt2) {
        uint32_t bh[4], bl[4];
        uint32_t off = (uint32_t)((wn * 64 + nt2 * 16 + b_row) * SB + k0 + b_col) * 2;
        ldsm_x4(stg + OBH * 2 + off, bh);
        ldsm_x4(stg + OBL * 2 + off, bl);
#pragma unroll
        for (int mt = 0; mt < 2; ++mt) {
          mma_f16(acc[mt][nt2 * 2], af[mt], bh);
          mma_f16(acc[mt][nt2 * 2], afs[mt], bl);
          mma_f16(acc[mt][nt2 * 2 + 1], af[mt], bh + 2);
          mma_f16(acc[mt][nt2 * 2 + 1], afs[mt], bl + 2);
        }
      }
    }
  }

#pragma unroll
  for (int mt = 0; mt < 2; ++mt) {
    int r0 = m0 + wm * 32 + mt * 16 + (lane >> 2);
#pragma unroll
    for (int nt = 0; nt < 8; ++nt) {
      int col = n0 + wn * 64 + nt * 8 + (lane & 3) * 2;
      float a0 = acc[mt][nt][0], a1 = acc[mt][nt][1];
      float b0 = acc[mt][nt][2], b1 = acc[mt][nt][3];
      if (MODE == 0) {
        float2 v0 = {a0, a1};
        float2 v1 = {b0, b1};
        *(float2*)(C + (size_t)r0 * N + col) = v0;
        *(float2*)(C + (size_t)(r0 + 8) * N + col) = v1;
      } else {
        int r1 = r0 + 8;
        if (col < DMODEL) {                    // Q: rope + scale -> fp16
          int p = (col & (HD - 1)) >> 1;       // pair index within head
          int s0r = r0 & (SEQ - 1);
          int s1r = r1 & (SEQ - 1);
          float c0 = fcos[s0r * 64 + p], sn0 = fsin[s0r * 64 + p];
          float c1 = fcos[s1r * 64 + p], sn1 = fsin[s1r * 64 + p];
          float q0 = (a0 * c0 - a1 * sn0) * QSCALE;
          float q1 = (a0 * sn0 + a1 * c0) * QSCALE;
          float q2 = (b0 * c1 - b1 * sn1) * QSCALE;
          float q3 = (b0 * sn1 + b1 * c1) * QSCALE;
          *(uint32_t*)(Qh + (size_t)r0 * DMODEL + col) = pack_f16(q0, q1);
          *(uint32_t*)(Qh + (size_t)r1 * DMODEL + col) = pack_f16(q2, q3);
        } else if (col < DMODEL + KVDIM) {     // K: rope -> split fp16
          int kc = col - DMODEL;
          int p = (kc & (HD - 1)) >> 1;
          int s0r = r0 & (SEQ - 1);
          int s1r = r1 & (SEQ - 1);
          float c0 = fcos[s0r * 64 + p], sn0 = fsin[s0r * 64 + p];
          float c1 = fcos[s1r * 64 + p], sn1 = fsin[s1r * 64 + p];
          float k0v = a0 * c0 - a1 * sn0;
          float k1v = a0 * sn0 + a1 * c0;
          float k2v = b0 * c1 - b1 * sn1;
          float k3v = b0 * sn1 + b1 * c1;
          *(uint32_t*)(Kh + (size_t)r0 * KVDIM + kc) = pack_f16(k0v, k1v);
          *(uint32_t*)(Kl + (size_t)r0 * KVDIM + kc) =
              pack_f16((k0v - f16_round(k0v)) * LO_SCALE,
                       (k1v - f16_round(k1v)) * LO_SCALE);
          *(uint32_t*)(Kh + (size_t)r1 * KVDIM + kc) = pack_f16(k2v, k3v);
          *(uint32_t*)(Kl + (size_t)r1 * KVDIM + kc) =
              pack_f16((k2v - f16_round(k2v)) * LO_SCALE,
                       (k3v - f16_round(k3v)) * LO_SCALE);
        } else {                               // V: split fp16
          int vc = col - DMODEL - KVDIM;
          *(uint32_t*)(Vh + (size_t)r0 * KVDIM + vc) = pack_f16(a0, a1);
          *(uint32_t*)(Vl + (size_t)r0 * KVDIM + vc) =
              pack_f16((a0 - f16_round(a0)) * LO_SCALE,
                       (a1 - f16_round(a1)) * LO_SCALE);
          *(uint32_t*)(Vh + (size_t)r1 * KVDIM + vc) = pack_f16(b0, b1);
          *(uint32_t*)(Vl + (size_t)r1 * KVDIM + vc) =
              pack_f16((b0 - f16_round(b0)) * LO_SCALE,
                       (b1 - f16_round(b1)) * LO_SCALE);
        }
      }
    }
  }
}

// ---------------------------------------------------------------------------
// Tensor-core flash attention, fp16 2-product, causal (unchanged).
// BLOCK_M=64 (4 warps x m16), BLOCK_N=64, D=128. 87 KB smem -> 2 CTAs/SM.
// ---------------------------------------------------------------------------
#define FSD 136                       // smem stride (elements)
#define FTE (64 * FSD)                // elements per tile
#define FA_SMEM (5 * FTE * 2)         // Q,Kh,Kl,Vh,Vl = 87040 B

__global__ __launch_bounds__(128) void fa_mma_kernel(
    const __half* __restrict__ qh, const __half* __restrict__ kh,
    const __half* __restrict__ kl, const __half* __restrict__ vh,
    const __half* __restrict__ vl, __half* __restrict__ ao) {
  extern __shared__ __half fsm[];
  const uint32_t sbase = smem_u32(fsm);
  const int tid = threadIdx.x;
  const int lane = tid & 31;
  const int w = tid >> 5;

  const int mt = gridDim.x - 1 - blockIdx.x;   // heavy tiles first
  const int m0 = mt * 64;
  const int h = blockIdx.y;
  const int b = blockIdx.z;
  const int g = h >> 2;

  const uint32_t QO = 0, KHO = FTE, KLO = 2 * FTE, VHO = 3 * FTE,
                 VLO = 4 * FTE;

  // --- async-load Q tile (pre-scaled fp16) ---
  {
    const int r = tid >> 4;
    const int cvec = (tid & 15) * 8;
#pragma unroll
    for (int it = 0; it < 8; ++it) {
      int row = r + it * 8;
      size_t gi = ((size_t)(b * SEQ + m0 + row) * NH + h) * HD + cvec;
      cpa16(sbase + (QO + (uint32_t)(row * FSD + cvec)) * 2, qh + gi);
    }
    cpa_commit();
  }

  float m_lo = -1e30f, m_hi = -1e30f, l_lo = 0.f, l_hi = 0.f;
  float oacc[16][4];
#pragma unroll
  for (int i = 0; i < 16; ++i)
#pragma unroll
    for (int j = 0; j < 4; ++j) oacc[i][j] = 0.f;

  const int a_row = lane & 15;
  const int a_col = (lane >> 4) * 8;
  const int b_row = (lane & 7) + ((lane & 16) >> 1);
  const int b_col = lane & 8;

  for (int t = 0; t <= mt; ++t) {
    const int n0 = t * 64;
    __syncthreads();                   // previous compute done
    {
      const int r = tid >> 4;
      const int cvec = (tid & 15) * 8;
#pragma unroll
      for (int it = 0; it < 8; ++it) {
        int row = r + it * 8;
        size_t gi = ((size_t)(b * SEQ + n0 + row) * NKV + g) * HD + cvec;
        uint32_t e = (uint32_t)(row * FSD + cvec) * 2;
        cpa16(sbase + KHO * 2 + e, kh + gi);
        cpa16(sbase + KLO * 2 + e, kl + gi);
        cpa16(sbase + VHO * 2 + e, vh + gi);
        cpa16(sbase + VLO * 2 + e, vl + gi);
      }
      cpa_commit();
    }
    cpa_wait0();
    __syncthreads();

    // --- S = Q @ (Kh + Kl*2^-10)^T ---
    float sacc[8][4];
#pragma unroll
    for (int i = 0; i < 8; ++i)
#pragma unroll
      for (int j = 0; j < 4; ++j) sacc[i][j] = 0.f;

#pragma unroll
    for (int kc = 0; kc < 8; ++kc) {
      uint32_t aq_off = (uint32_t)((w * 16 + a_row) * FSD + kc * 16 + a_col) * 2;
      uint32_t aq[4], aqs[4];
      ldsm_x4(sbase + QO * 2 + aq_off, aq);
#pragma unroll
      for (int qq = 0; qq < 4; ++qq) aqs[qq] = hscale(aq[qq]);
#pragma unroll
      for (int np = 0; np < 4; ++np) {
        uint32_t bo = (uint32_t)((np * 16 + b_row) * FSD + kc * 16 + b_col) * 2;
        uint32_t bh[4], bl[4];
        ldsm_x4(sbase + KHO * 2 + bo, bh);
        ldsm_x4(sbase + KLO * 2 + bo, bl);
        mma_f16(sacc[np * 2], aq, bh);
        mma_f16(sacc[np * 2], aqs, bl);
        mma_f16(sacc[np * 2 + 1], aq, bh + 2);
        mma_f16(sacc[np * 2 + 1], aqs, bl + 2);
      }
    }

    if (t == mt) {
      int row_lo = w * 16 + (lane >> 2);
      int row_hi = row_lo + 8;
#pragma unroll
      for (int nt = 0; nt < 8; ++nt) {
        int c0 = nt * 8 + (lane & 3) * 2;
        if (c0 > row_lo) sacc[nt][0] = -1e30f;
        if (c0 + 1 > row_lo) sacc[nt][1] = -1e30f;
        if (c0 > row_hi) sacc[nt][2] = -1e30f;
        if (c0 + 1 > row_hi) sacc[nt][3] = -1e30f;
      }
    }

    // --- online softmax ---
    float rmax_lo = -1e30f, rmax_hi = -1e30f;
#pragma unroll
    for (int nt = 0; nt < 8; ++nt) {
      rmax_lo = fmaxf(rmax_lo, fmaxf(sacc[nt][0], sacc[nt][1]));
      rmax_hi = fmaxf(rmax_hi, fmaxf(sacc[nt][2], sacc[nt][3]));
    }
#pragma unroll
    for (int d = 1; d < 4; d <<= 1) {
      rmax_lo = fmaxf(rmax_lo, __shfl_xor_sync(0xffffffffu, rmax_lo, d));
      rmax_hi = fmaxf(rmax_hi, __shfl_xor_sync(0xffffffffu, rmax_hi, d));
    }
    float mn_lo = fmaxf(m_lo, rmax_lo);
    float mn_hi = fmaxf(m_hi, rmax_hi);
    float f_lo = __expf(m_lo - mn_lo);
    float f_hi = __expf(m_hi - mn_hi);
    m_lo = mn_lo; m_hi = mn_hi;

    float rsum_lo = 0.f, rsum_hi = 0.f;
#pragma unroll
    for (int nt = 0; nt < 8; ++nt) {
      sacc[nt][0] = __expf(sacc[nt][0] - mn_lo);
      sacc[nt][1] = __expf(sacc[nt][1] - mn_lo);
      sacc[nt][2] = __expf(sacc[nt][2] - mn_hi);
      sacc[nt][3] = __expf(sacc[nt][3] - mn_hi);
      rsum_lo += sacc[nt][0] + sacc[nt][1];
      rsum_hi += sacc[nt][2] + sacc[nt][3];
    }
#pragma unroll
    for (int d = 1; d < 4; d <<= 1) {
      rsum_lo += __shfl_xor_sync(0xffffffffu, rsum_lo, d);
      rsum_hi += __shfl_xor_sync(0xffffffffu, rsum_hi, d);
    }
    l_lo = l_lo * f_lo + rsum_lo;
    l_hi = l_hi * f_hi + rsum_hi;
#pragma unroll
    for (int i = 0; i < 16; ++i) {
      oacc[i][0] *= f_lo; oacc[i][1] *= f_lo;
      oacc[i][2] *= f_hi; oacc[i][3] *= f_hi;
    }

    // --- O += P @ (Vh + Vl*2^-10) ---
#pragma unroll
    for (int kt = 0; kt < 4; ++kt) {
      const float* s0 = sacc[2 * kt];
      const float* s1 = sacc[2 * kt + 1];
      uint32_t ph[4], ps[4];
      ph[0] = pack_f16(s0[0], s0[1]);
      ph[1] = pack_f16(s0[2], s0[3]);
      ph[2] = pack_f16(s1[0], s1[1]);
      ph[3] = pack_f16(s1[2], s1[3]);
      ps[0] = pack_f16(s0[0] * INV_LO_SCALE, s0[1] * INV_LO_SCALE);
      ps[1] = pack_f16(s0[2] * INV_LO_SCALE, s0[3] * INV_LO_SCALE);
      ps[2] = pack_f16(s1[0] * INV_LO_SCALE, s1[1] * INV_LO_SCALE);
      ps[3] = pack_f16(s1[2] * INV_LO_SCALE, s1[3] * INV_LO_SCALE);
#pragma unroll
      for (int dp = 0; dp < 8; ++dp) {
        uint32_t vo = (uint32_t)((kt * 16 + (lane & 15)) * FSD + dp * 16 +
                                 ((lane >> 4) << 3)) * 2;
        uint32_t vhf[4], vlf[4];
        ldsm_x4_t(sbase + VHO * 2 + vo, vhf);
        ldsm_x4_t(sbase + VLO * 2 + vo, vlf);
        mma_f16(oacc[dp * 2], ph, vhf);
        mma_f16(oacc[dp * 2], ps, vlf);
        mma_f16(oacc[dp * 2 + 1], ph, vhf + 2);
        mma_f16(oacc[dp * 2 + 1], ps, vlf + 2);
      }
    }
  }

  // --- epilogue: normalize, round to fp16, write [b,s,h,d] ---
  float inv_lo = 1.f / l_lo;
  float inv_hi = 1.f / l_hi;
  int r_lo = m0 + w * 16 + (lane >> 2);
  int r_hi = r_lo + 8;
#pragma unroll
  for (int dt = 0; dt < 16; ++dt) {
    int col = dt * 8 + (lane & 3) * 2;
    size_t i0 = ((size_t)(b * SEQ + r_lo) * NH + h) * HD + col;
    size_t i1 = ((size_t)(b * SEQ + r_hi) * NH + h) * HD + col;
    *(uint32_t*)(ao + i0) = pack_f16(oacc[dt][0] * inv_lo, oacc[dt][1] * inv_lo);
    *(uint32_t*)(ao + i1) = pack_f16(oacc[dt][2] * inv_hi, oacc[dt][3] * inv_hi);
  }
}

// ---------------------------------------------------------------------------
// Launch
// ---------------------------------------------------------------------------
extern "C" void kernel_launch(void* const* d_in, const int* in_sizes, int n_in,
                              void* d_out, int out_size) {
  const float* x    = (const float*)d_in[0];
  const float* fcos = (const float*)d_in[1];
  const float* fsin = (const float*)d_in[2];
  // d_in[3] = mask (causal mask applied analytically)
  const float* wq = (const float*)d_in[4];
  const float* wk = (const float*)d_in[5];
  const float* wv = (const float*)d_in[6];
  const float* wo = (const float*)d_in[7];
  float* out = (float*)d_out;

  __half *xh, *aoh, *qh, *kh, *kl, *vh, *vl;
  __half *wqkvh, *wqkvl, *woh, *wol;
  cudaGetSymbolAddress((void**)&xh, g_xh);
  cudaGetSymbolAddress((void**)&aoh, g_aoh);
  cudaGetSymbolAddress((void**)&qh, g_qh);
  cudaGetSymbolAddress((void**)&kh, g_kh);
  cudaGetSymbolAddress((void**)&kl, g_kl);
  cudaGetSymbolAddress((void**)&vh, g_vh);
  cudaGetSymbolAddress((void**)&vl, g_vl);
  cudaGetSymbolAddress((void**)&wqkvh, g_wqkv_h);
  cudaGetSymbolAddress((void**)&wqkvl, g_wqkv_l);
  cudaGetSymbolAddress((void**)&woh, g_wo_h);
  cudaGetSymbolAddress((void**)&wol, g_wo_l);

  static bool attr_done = false;
  if (!attr_done) {
    cudaFuncSetAttribute(gemm_mma_kernel<0>,
                         cudaFuncAttributeMaxDynamicSharedMemorySize, GEMM_SMEM);
    cudaFuncSetAttribute(gemm_mma_kernel<1>,
                         cudaFuncAttributeMaxDynamicSharedMemorySize, GEMM_SMEM);
    cudaFuncSetAttribute(fa_mma_kernel,
                         cudaFuncAttributeMaxDynamicSharedMemorySize, FA_SMEM);
    attr_done = true;
  }

  // round x / transpose+split weights into combined QKV + wo
  {
    int nx = MTOK * DMODEL;
    round_kernel<<<(nx + 255) / 256, 256>>>(x, xh, nx);
    dim3 blk(32, 8);
    transpose_split_kernel<<<dim3(DMODEL / 32, DMODEL / 32), blk>>>(
        wq, wqkvh, wqkvl, DMODEL, DMODEL);
    transpose_split_kernel<<<dim3(KVDIM / 32, DMODEL / 32), blk>>>(
        wk, wqkvh + (size_t)DMODEL * DMODEL, wqkvl + (size_t)DMODEL * DMODEL,
        DMODEL, KVDIM);
    transpose_split_kernel<<<dim3(KVDIM / 32, DMODEL / 32), blk>>>(
        wv, wqkvh + (size_t)(DMODEL + KVDIM) * DMODEL,
        wqkvl + (size_t)(DMODEL + KVDIM) * DMODEL, DMODEL, KVDIM);
    transpose_split_kernel<<<dim3(DMODEL / 32, DMODEL / 32), blk>>>(
        wo, woh, wol, DMODEL, DMODEL);
  }

  // fused QKV projection + in-register RoPE (one launch, 768 CTAs)
  gemm_mma_kernel<1><<<dim3(QKVN / 128, MTOK / 128), 256, GEMM_SMEM>>>(
      xh, wqkvh, wqkvl, nullptr, QKVN, DMODEL, fcos, fsin,
      qh, kh, kl, vh, vl);

  // Tensor-core flash attention
  fa_mma_kernel<<<dim3(SEQ / 64, NH, BATCH), 128, FA_SMEM>>>(
      qh, kh, kl, vh, vl, aoh);

  // Output projection
  gemm_mma_kernel<0><<<dim3(DMODEL / 128, MTOK / 128), 256, GEMM_SMEM>>>(
      aoh, woh, wol, out, DMODEL, DMODEL, nullptr, nullptr,
      nullptr, nullptr, nullptr, nullptr, nullptr);
}

// round 16
// speedup vs baseline: 2.0401x; 1.2592x over previous
#include <cuda_runtime.h>
#include <cuda_fp16.h>
#include <cstdint>
#include <math.h>

// Problem dims (fixed by reference)
#define BATCH 2
#define SEQ 2048
#define DMODEL 2048
#define NH 16
#define NKV 4
#define HD 128
#define MTOK (BATCH * SEQ)          // 4096 tokens
#define KVDIM (NKV * HD)            // 512
#define QKVN (DMODEL + 2 * KVDIM)   // 3072

// ---------------------------------------------------------------------------
// Scratch (device globals; runtime allocation is forbidden)
// ---------------------------------------------------------------------------
__device__ __half g_xh[MTOK * DMODEL];
__device__ __half g_aoh[MTOK * DMODEL];
__device__ __half g_qh[MTOK * NH * HD];
__device__ __half g_kh[MTOK * KVDIM];
__device__ __half g_kl[MTOK * KVDIM];
__device__ __half g_vh[MTOK * KVDIM];
// combined QKV weights [3072, 2048]
__device__ __half g_wqkv_h[QKVN * DMODEL];
__device__ __half g_wqkv_l[QKVN * DMODEL];
__device__ __half g_wo_h[DMODEL * DMODEL];

#define LO_SCALE 1024.0f
#define HSC2 0x14001400u                     // fp16x2 constant 2^-10
#define QSCALE 0.08838834764831845f         // 1/sqrt(128)

// ---------------------------------------------------------------------------
// helpers
// ---------------------------------------------------------------------------
__device__ __forceinline__ uint32_t smem_u32(const void* p) {
  uint32_t a;
  asm("{ .reg .u64 t; cvta.to.shared.u64 t, %1; cvt.u32.u64 %0, t; }"
      : "=r"(a) : "l"(p));
  return a;
}
__device__ __forceinline__ void cpa16(uint32_t s, const void* g) {
  asm volatile("cp.async.cg.shared.global [%0], [%1], 16;"
               :: "r"(s), "l"(g) : "memory");
}
__device__ __forceinline__ void cpa_commit() {
  asm volatile("cp.async.commit_group;" ::: "memory");
}
__device__ __forceinline__ void cpa_wait0() {
  asm volatile("cp.async.wait_group 0;" ::: "memory");
}
__device__ __forceinline__ void ldsm_x4(uint32_t addr, uint32_t* r) {
  asm volatile("ldmatrix.sync.aligned.m8n8.x4.shared.b16 {%0,%1,%2,%3}, [%4];"
               : "=r"(r[0]), "=r"(r[1]), "=r"(r[2]), "=r"(r[3]) : "r"(addr));
}
__device__ __forceinline__ void ldsm_x4_t(uint32_t addr, uint32_t* r) {
  asm volatile("ldmatrix.sync.aligned.m8n8.x4.trans.shared.b16 {%0,%1,%2,%3}, [%4];"
               : "=r"(r[0]), "=r"(r[1]), "=r"(r[2]), "=r"(r[3]) : "r"(addr));
}
__device__ __forceinline__ void mma_f16(float* d, const uint32_t* a,
                                        const uint32_t* b) {
  asm volatile(
      "mma.sync.aligned.m16n8k16.row.col.f32.f16.f16.f32 "
      "{%0,%1,%2,%3}, {%4,%5,%6,%7}, {%8,%9}, {%0,%1,%2,%3};"
      : "+f"(d[0]), "+f"(d[1]), "+f"(d[2]), "+f"(d[3])
      : "r"(a[0]), "r"(a[1]), "r"(a[2]), "r"(a[3]), "r"(b[0]), "r"(b[1]));
}
__device__ __forceinline__ uint32_t pack_f16(float a, float b) {
  uint32_t r;
  asm("cvt.rn.f16x2.f32 %0, %1, %2;" : "=r"(r) : "f"(b), "f"(a));
  return r;
}
__device__ __forceinline__ float f16_round(float f) {
  return __half2float(__float2half(f));
}
__device__ __forceinline__ uint32_t hscale(uint32_t x) {
  uint32_t r;
  asm("mul.f16x2 %0, %1, %2;" : "=r"(r) : "r"(x), "r"(HSC2));
  return r;
}

// ---------------------------------------------------------------------------
// Conversion kernels
// ---------------------------------------------------------------------------
__global__ void round_kernel(const float* __restrict__ src,
                             __half* __restrict__ dst, int n) {
  int i = blockIdx.x * blockDim.x + threadIdx.x;
  if (i >= n) return;
  dst[i] = __float2half(src[i]);
}

// transpose + split (hi + residual*2^10)
__global__ void transpose_split_kernel(const float* __restrict__ w,
                                       __half* __restrict__ th,
                                       __half* __restrict__ tl,
                                       int K, int N) {
  __shared__ float tile[32][33];
  int nx = blockIdx.x * 32 + threadIdx.x;
  int k0 = blockIdx.y * 32;
  for (int i = threadIdx.y; i < 32; i += 8)
    tile[i][threadIdx.x] = w[(size_t)(k0 + i) * N + nx];
  __syncthreads();
  for (int j = threadIdx.y; j < 32; j += 8) {
    int n = blockIdx.x * 32 + j;
    int kk = k0 + threadIdx.x;
    float f = tile[threadIdx.x][j];
    float h = f16_round(f);
    th[(size_t)n * K + kk] = __float2half(h);
    tl[(size_t)n * K + kk] = __float2half((f - h) * LO_SCALE);
  }
}

// transpose + single round (hi only) — for wo
__global__ void transpose_round_kernel(const float* __restrict__ w,
                                       __half* __restrict__ th, int K, int N) {
  __shared__ float tile[32][33];
  int nx = blockIdx.x * 32 + threadIdx.x;
  int k0 = blockIdx.y * 32;
  for (int i = threadIdx.y; i < 32; i += 8)
    tile[i][threadIdx.x] = w[(size_t)(k0 + i) * N + nx];
  __syncthreads();
  for (int j = threadIdx.y; j < 32; j += 8) {
    int n = blockIdx.x * 32 + j;
    int kk = k0 + threadIdx.x;
    th[(size_t)n * K + kk] = __float2half(tile[threadIdx.x][j]);
  }
}

// ---------------------------------------------------------------------------
// mma.sync fp16 GEMM, 2-stage cp.async pipeline, BK=64.
// MODE 0: single-product (Bh only), fp32 C[M,N] — out-projection.
// MODE 1: 2-product (Bh + Bl*2^-10), fused QKV epilogue with in-register RoPE.
// 128x128 CTA tile, 256 thr, 8 warps (warp tile 32x64).
// ---------------------------------------------------------------------------
#define SB 72
#define T2E (128 * SB)
#define STG_E (3 * T2E)
#define GEMM_SMEM (2 * STG_E * 2)      // 110592 B (MODE 1; MODE 0 uses subset)

template <int MODE>
__global__ __launch_bounds__(256, 2) void gemm_mma_kernel(
    const __half* __restrict__ A, const __half* __restrict__ Bh,
    const __half* __restrict__ Bl, float* __restrict__ C, int N, int K,
    const float* __restrict__ fcos, const float* __restrict__ fsin,
    __half* __restrict__ Qh, __half* __restrict__ Kh, __half* __restrict__ Kl,
    __half* __restrict__ Vh) {
  extern __shared__ __half smb[];
  const int tid = threadIdx.x;
  const int lane = tid & 31;
  const int wid = tid >> 5;
  const int wm = wid & 3;
  const int wn = wid >> 2;
  const int m0 = blockIdx.y * 128;
  const int n0 = blockIdx.x * 128;
  const uint32_t sbase = smem_u32(smb);

  // stage layout: MODE1: A, Bh, Bl; MODE0: A, Bh (Bl slot unused)
  const int TILES = (MODE == 1) ? 3 : 2;
  const uint32_t OA = 0, OBH = T2E, OBL = 2 * T2E;
  const uint32_t STGB = (uint32_t)(TILES * T2E) * 2;   // stage stride bytes

  float acc[2][8][4];
#pragma unroll
  for (int i = 0; i < 2; ++i)
#pragma unroll
    for (int j = 0; j < 8; ++j)
#pragma unroll
      for (int q = 0; q < 4; ++q) acc[i][j][q] = 0.f;

  const int a_row = lane & 15;
  const int a_col = (lane >> 4) * 8;
  const int b_row = (lane & 7) + ((lane & 16) >> 1);
  const int b_col = lane & 8;

  const int nchunks = K >> 6;

  {
#pragma unroll
    for (int it = 0; it < 4; ++it) {
      int v = tid + it * 256;
      int r = v >> 3;
      int cv = (v & 7) * 8;
      const size_t ga = (size_t)(m0 + r) * K + cv;
      const size_t gb = (size_t)(n0 + r) * K + cv;
      uint32_t so = (uint32_t)(r * SB + cv) * 2;
      cpa16(sbase + OA * 2 + so, A + ga);
      cpa16(sbase + OBH * 2 + so, Bh + gb);
      if (MODE == 1) cpa16(sbase + OBL * 2 + so, Bl + gb);
    }
    cpa_commit();
  }

  for (int c = 0; c < nchunks; ++c) {
    cpa_wait0();
    __syncthreads();
    if (c + 1 < nchunks) {
      const int k0g = (c + 1) << 6;
      const uint32_t stb = sbase + ((c + 1) & 1) * STGB;
#pragma unroll
      for (int it = 0; it < 4; ++it) {
        int v = tid + it * 256;
        int r = v >> 3;
        int cv = (v & 7) * 8;
        const size_t ga = (size_t)(m0 + r) * K + k0g + cv;
        const size_t gb = (size_t)(n0 + r) * K + k0g + cv;
        uint32_t so = (uint32_t)(r * SB + cv) * 2;
        cpa16(stb + OA * 2 + so, A + ga);
        cpa16(stb + OBH * 2 + so, Bh + gb);
        if (MODE == 1) cpa16(stb + OBL * 2 + so, Bl + gb);
      }
      cpa_commit();
    }

    const uint32_t stg = sbase + (c & 1) * STGB;
#pragma unroll
    for (int s = 0; s < 4; ++s) {
      const int k0 = s * 16;
      uint32_t af[2][4], afs[2][4];
#pragma unroll
      for (int mt = 0; mt < 2; ++mt) {
        uint32_t off = (uint32_t)((wm * 32 + mt * 16 + a_row) * SB + k0 + a_col) * 2;
        ldsm_x4(stg + OA * 2 + off, af[mt]);
        if (MODE == 1) {
#pragma unroll
          for (int qq = 0; qq < 4; ++qq) afs[mt][qq] = hscale(af[mt][qq]);
        }
      }
#pragma unroll
      for (int nt2 = 0; nt2 < 4; ++nt2) {
        uint32_t bh[4], bl[4];
        uint32_t off = (uint32_t)((wn * 64 + nt2 * 16 + b_row) * SB + k0 + b_col) * 2;
        ldsm_x4(stg + OBH * 2 + off, bh);
        if (MODE == 1) ldsm_x4(stg + OBL * 2 + off, bl);
#pragma unroll
        for (int mt = 0; mt < 2; ++mt) {
          mma_f16(acc[mt][nt2 * 2], af[mt], bh);
          mma_f16(acc[mt][nt2 * 2 + 1], af[mt], bh + 2);
          if (MODE == 1) {
            mma_f16(acc[mt][nt2 * 2], afs[mt], bl);
            mma_f16(acc[mt][nt2 * 2 + 1], afs[mt], bl + 2);
          }
        }
      }
    }
  }

#pragma unroll
  for (int mt = 0; mt < 2; ++mt) {
    int r0 = m0 + wm * 32 + mt * 16 + (lane >> 2);
#pragma unroll
    for (int nt = 0; nt < 8; ++nt) {
      int col = n0 + wn * 64 + nt * 8 + (lane & 3) * 2;
      float a0 = acc[mt][nt][0], a1 = acc[mt][nt][1];
      float b0 = acc[mt][nt][2], b1 = acc[mt][nt][3];
      if (MODE == 0) {
        float2 v0 = {a0, a1};
        float2 v1 = {b0, b1};
        *(float2*)(C + (size_t)r0 * N + col) = v0;
        *(float2*)(C + (size_t)(r0 + 8) * N + col) = v1;
      } else {
        int r1 = r0 + 8;
        if (col < DMODEL) {                    // Q: rope + scale -> fp16
          int p = (col & (HD - 1)) >> 1;
          int s0r = r0 & (SEQ - 1);
          int s1r = r1 & (SEQ - 1);
          float c0 = fcos[s0r * 64 + p], sn0 = fsin[s0r * 64 + p];
          float c1 = fcos[s1r * 64 + p], sn1 = fsin[s1r * 64 + p];
          float q0 = (a0 * c0 - a1 * sn0) * QSCALE;
          float q1 = (a0 * sn0 + a1 * c0) * QSCALE;
          float q2 = (b0 * c1 - b1 * sn1) * QSCALE;
          float q3 = (b0 * sn1 + b1 * c1) * QSCALE;
          *(uint32_t*)(Qh + (size_t)r0 * DMODEL + col) = pack_f16(q0, q1);
          *(uint32_t*)(Qh + (size_t)r1 * DMODEL + col) = pack_f16(q2, q3);
        } else if (col < DMODEL + KVDIM) {     // K: rope -> split fp16
          int kc = col - DMODEL;
          int p = (kc & (HD - 1)) >> 1;
          int s0r = r0 & (SEQ - 1);
          int s1r = r1 & (SEQ - 1);
          float c0 = fcos[s0r * 64 + p], sn0 = fsin[s0r * 64 + p];
          float c1 = fcos[s1r * 64 + p], sn1 = fsin[s1r * 64 + p];
          float k0v = a0 * c0 - a1 * sn0;
          float k1v = a0 * sn0 + a1 * c0;
          float k2v = b0 * c1 - b1 * sn1;
          float k3v = b0 * sn1 + b1 * c1;
          *(uint32_t*)(Kh + (size_t)r0 * KVDIM + kc) = pack_f16(k0v, k1v);
          *(uint32_t*)(Kl + (size_t)r0 * KVDIM + kc) =
              pack_f16((k0v - f16_round(k0v)) * LO_SCALE,
                       (k1v - f16_round(k1v)) * LO_SCALE);
          *(uint32_t*)(Kh + (size_t)r1 * KVDIM + kc) = pack_f16(k2v, k3v);
          *(uint32_t*)(Kl + (size_t)r1 * KVDIM + kc) =
              pack_f16((k2v - f16_round(k2v)) * LO_SCALE,
                       (k3v - f16_round(k3v)) * LO_SCALE);
        } else {                               // V: single fp16
          int vc = col - DMODEL - KVDIM;
          *(uint32_t*)(Vh + (size_t)r0 * KVDIM + vc) = pack_f16(a0, a1);
          *(uint32_t*)(Vh + (size_t)r1 * KVDIM + vc) = pack_f16(b0, b1);
        }
      }
    }
  }
}

// ---------------------------------------------------------------------------
// Tensor-core flash attention, causal. S: fp16 2-product (K split);
// P·V: single product (V single-rounded).
// BLOCK_M=64 (4 warps x m16), BLOCK_N=64, D=128. 69.6 KB smem.
// ---------------------------------------------------------------------------
#define FSD 136                       // smem stride (elements)
#define FTE (64 * FSD)                // elements per tile
#define FA_SMEM (4 * FTE * 2)         // Q,Kh,Kl,Vh = 69632 B

__global__ __launch_bounds__(128) void fa_mma_kernel(
    const __half* __restrict__ qh, const __half* __restrict__ kh,
    const __half* __restrict__ kl, const __half* __restrict__ vh,
    __half* __restrict__ ao) {
  extern __shared__ __half fsm[];
  const uint32_t sbase = smem_u32(fsm);
  const int tid = threadIdx.x;
  const int lane = tid & 31;
  const int w = tid >> 5;

  const int mt = gridDim.x - 1 - blockIdx.x;   // heavy tiles first
  const int m0 = mt * 64;
  const int h = blockIdx.y;
  const int b = blockIdx.z;
  const int g = h >> 2;

  const uint32_t QO = 0, KHO = FTE, KLO = 2 * FTE, VHO = 3 * FTE;

  // --- async-load Q tile (pre-scaled fp16) ---
  {
    const int r = tid >> 4;
    const int cvec = (tid & 15) * 8;
#pragma unroll
    for (int it = 0; it < 8; ++it) {
      int row = r + it * 8;
      size_t gi = ((size_t)(b * SEQ + m0 + row) * NH + h) * HD + cvec;
      cpa16(sbase + (QO + (uint32_t)(row * FSD + cvec)) * 2, qh + gi);
    }
    cpa_commit();
  }

  float m_lo = -1e30f, m_hi = -1e30f, l_lo = 0.f, l_hi = 0.f;
  float oacc[16][4];
#pragma unroll
  for (int i = 0; i < 16; ++i)
#pragma unroll
    for (int j = 0; j < 4; ++j) oacc[i][j] = 0.f;

  const int a_row = lane & 15;
  const int a_col = (lane >> 4) * 8;
  const int b_row = (lane & 7) + ((lane & 16) >> 1);
  const int b_col = lane & 8;

  for (int t = 0; t <= mt; ++t) {
    const int n0 = t * 64;
    __syncthreads();                   // previous compute done
    {
      const int r = tid >> 4;
      const int cvec = (tid & 15) * 8;
#pragma unroll
      for (int it = 0; it < 8; ++it) {
        int row = r + it * 8;
        size_t gi = ((size_t)(b * SEQ + n0 + row) * NKV + g) * HD + cvec;
        uint32_t e = (uint32_t)(row * FSD + cvec) * 2;
        cpa16(sbase + KHO * 2 + e, kh + gi);
        cpa16(sbase + KLO * 2 + e, kl + gi);
        cpa16(sbase + VHO * 2 + e, vh + gi);
      }
      cpa_commit();
    }
    cpa_wait0();
    __syncthreads();

    // --- S = Q @ (Kh + Kl*2^-10)^T ---
    float sacc[8][4];
#pragma unroll
    for (int i = 0; i < 8; ++i)
#pragma unroll
      for (int j = 0; j < 4; ++j) sacc[i][j] = 0.f;

#pragma unroll
    for (int kc = 0; kc < 8; ++kc) {
      uint32_t aq_off = (uint32_t)((w * 16 + a_row) * FSD + kc * 16 + a_col) * 2;
      uint32_t aq[4], aqs[4];
      ldsm_x4(sbase + QO * 2 + aq_off, aq);
#pragma unroll
      for (int qq = 0; qq < 4; ++qq) aqs[qq] = hscale(aq[qq]);
#pragma unroll
      for (int np = 0; np < 4; ++np) {
        uint32_t bo = (uint32_t)((np * 16 + b_row) * FSD + kc * 16 + b_col) * 2;
        uint32_t bh[4], bl[4];
        ldsm_x4(sbase + KHO * 2 + bo, bh);
        ldsm_x4(sbase + KLO * 2 + bo, bl);
        mma_f16(sacc[np * 2], aq, bh);
        mma_f16(sacc[np * 2], aqs, bl);
        mma_f16(sacc[np * 2 + 1], aq, bh + 2);
        mma_f16(sacc[np * 2 + 1], aqs, bl + 2);
      }
    }

    if (t == mt) {
      int row_lo = w * 16 + (lane >> 2);
      int row_hi = row_lo + 8;
#pragma unroll
      for (int nt = 0; nt < 8; ++nt) {
        int c0 = nt * 8 + (lane & 3) * 2;
        if (c0 > row_lo) sacc[nt][0] = -1e30f;
        if (c0 + 1 > row_lo) sacc[nt][1] = -1e30f;
        if (c0 > row_hi) sacc[nt][2] = -1e30f;
        if (c0 + 1 > row_hi) sacc[nt][3] = -1e30f;
      }
    }

    // --- online softmax ---
    float rmax_lo = -1e30f, rmax_hi = -1e30f;
#pragma unroll
    for (int nt = 0; nt < 8; ++nt) {
      rmax_lo = fmaxf(rmax_lo, fmaxf(sacc[nt][0], sacc[nt][1]));
      rmax_hi = fmaxf(rmax_hi, fmaxf(sacc[nt][2], sacc[nt][3]));
    }
#pragma unroll
    for (int d = 1; d < 4; d <<= 1) {
      rmax_lo = fmaxf(rmax_lo, __shfl_xor_sync(0xffffffffu, rmax_lo, d));
      rmax_hi = fmaxf(rmax_hi, __shfl_xor_sync(0xffffffffu, rmax_hi, d));
    }
    float mn_lo = fmaxf(m_lo, rmax_lo);
    float mn_hi = fmaxf(m_hi, rmax_hi);
    float f_lo = __expf(m_lo - mn_lo);
    float f_hi = __expf(m_hi - mn_hi);
    m_lo = mn_lo; m_hi = mn_hi;

    float rsum_lo = 0.f, rsum_hi = 0.f;
#pragma unroll
    for (int nt = 0; nt < 8; ++nt) {
      sacc[nt][0] = __expf(sacc[nt][0] - mn_lo);
      sacc[nt][1] = __expf(sacc[nt][1] - mn_lo);
      sacc[nt][2] = __expf(sacc[nt][2] - mn_hi);
      sacc[nt][3] = __expf(sacc[nt][3] - mn_hi);
      rsum_lo += sacc[nt][0] + sacc[nt][1];
      rsum_hi += sacc[nt][2] + sacc[nt][3];
    }
#pragma unroll
    for (int d = 1; d < 4; d <<= 1) {
      rsum_lo += __shfl_xor_sync(0xffffffffu, rsum_lo, d);
      rsum_hi += __shfl_xor_sync(0xffffffffu, rsum_hi, d);
    }
    l_lo = l_lo * f_lo + rsum_lo;
    l_hi = l_hi * f_hi + rsum_hi;
#pragma unroll
    for (int i = 0; i < 16; ++i) {
      oacc[i][0] *= f_lo; oacc[i][1] *= f_lo;
      oacc[i][2] *= f_hi; oacc[i][3] *= f_hi;
    }

    // --- O += P @ Vh (single product) ---
#pragma unroll
    for (int kt = 0; kt < 4; ++kt) {
      const float* s0 = sacc[2 * kt];
      const float* s1 = sacc[2 * kt + 1];
      uint32_t ph[4];
      ph[0] = pack_f16(s0[0], s0[1]);
      ph[1] = pack_f16(s0[2], s0[3]);
      ph[2] = pack_f16(s1[0], s1[1]);
      ph[3] = pack_f16(s1[2], s1[3]);
#pragma unroll
      for (int dp = 0; dp < 8; ++dp) {
        uint32_t vo = (uint32_t)((kt * 16 + (lane & 15)) * FSD + dp * 16 +
                                 ((lane >> 4) << 3)) * 2;
        uint32_t vhf[4];
        ldsm_x4_t(sbase + VHO * 2 + vo, vhf);
        mma_f16(oacc[dp * 2], ph, vhf);
        mma_f16(oacc[dp * 2 + 1], ph, vhf + 2);
      }
    }
  }

  // --- epilogue: normalize, round to fp16, write [b,s,h,d] ---
  float inv_lo = 1.f / l_lo;
  float inv_hi = 1.f / l_hi;
  int r_lo = m0 + w * 16 + (lane >> 2);
  int r_hi = r_lo + 8;
#pragma unroll
  for (int dt = 0; dt < 16; ++dt) {
    int col = dt * 8 + (lane & 3) * 2;
    size_t i0 = ((size_t)(b * SEQ + r_lo) * NH + h) * HD + col;
    size_t i1 = ((size_t)(b * SEQ + r_hi) * NH + h) * HD + col;
    *(uint32_t*)(ao + i0) = pack_f16(oacc[dt][0] * inv_lo, oacc[dt][1] * inv_lo);
    *(uint32_t*)(ao + i1) = pack_f16(oacc[dt][2] * inv_hi, oacc[dt][3] * inv_hi);
  }
}

// ---------------------------------------------------------------------------
// Launch
// ---------------------------------------------------------------------------
extern "C" void kernel_launch(void* const* d_in, const int* in_sizes, int n_in,
                              void* d_out, int out_size) {
  const float* x    = (const float*)d_in[0];
  const float* fcos = (const float*)d_in[1];
  const float* fsin = (const float*)d_in[2];
  // d_in[3] = mask (causal mask applied analytically)
  const float* wq = (const float*)d_in[4];
  const float* wk = (const float*)d_in[5];
  const float* wv = (const float*)d_in[6];
  const float* wo = (const float*)d_in[7];
  float* out = (float*)d_out;

  __half *xh, *aoh, *qh, *kh, *kl, *vh;
  __half *wqkvh, *wqkvl, *woh;
  cudaGetSymbolAddress((void**)&xh, g_xh);
  cudaGetSymbolAddress((void**)&aoh, g_aoh);
  cudaGetSymbolAddress((void**)&qh, g_qh);
  cudaGetSymbolAddress((void**)&kh, g_kh);
  cudaGetSymbolAddress((void**)&kl, g_kl);
  cudaGetSymbolAddress((void**)&vh, g_vh);
  cudaGetSymbolAddress((void**)&wqkvh, g_wqkv_h);
  cudaGetSymbolAddress((void**)&wqkvl, g_wqkv_l);
  cudaGetSymbolAddress((void**)&woh, g_wo_h);

  static bool attr_done = false;
  if (!attr_done) {
    cudaFuncSetAttribute(gemm_mma_kernel<0>,
                         cudaFuncAttributeMaxDynamicSharedMemorySize, GEMM_SMEM);
    cudaFuncSetAttribute(gemm_mma_kernel<1>,
                         cudaFuncAttributeMaxDynamicSharedMemorySize, GEMM_SMEM);
    cudaFuncSetAttribute(fa_mma_kernel,
                         cudaFuncAttributeMaxDynamicSharedMemorySize, FA_SMEM);
    attr_done = true;
  }

  // round x / transpose+split weights into combined QKV; wo single-rounded
  {
    int nx = MTOK * DMODEL;
    round_kernel<<<(nx + 255) / 256, 256>>>(x, xh, nx);
    dim3 blk(32, 8);
    transpose_split_kernel<<<dim3(DMODEL / 32, DMODEL / 32), blk>>>(
        wq, wqkvh, wqkvl, DMODEL, DMODEL);
    transpose_split_kernel<<<dim3(KVDIM / 32, DMODEL / 32), blk>>>(
        wk, wqkvh + (size_t)DMODEL * DMODEL, wqkvl + (size_t)DMODEL * DMODEL,
        DMODEL, KVDIM);
    transpose_split_kernel<<<dim3(KVDIM / 32, DMODEL / 32), blk>>>(
        wv, wqkvh + (size_t)(DMODEL + KVDIM) * DMODEL,
        wqkvl + (size_t)(DMODEL + KVDIM) * DMODEL, DMODEL, KVDIM);
    transpose_round_kernel<<<dim3(DMODEL / 32, DMODEL / 32), blk>>>(
        wo, woh, DMODEL, DMODEL);
  }

  // fused QKV projection + in-register RoPE (2-product)
  gemm_mma_kernel<1><<<dim3(QKVN / 128, MTOK / 128), 256, GEMM_SMEM>>>(
      xh, wqkvh, wqkvl, nullptr, QKVN, DMODEL, fcos, fsin,
      qh, kh, kl, vh);

  // Tensor-core flash attention
  fa_mma_kernel<<<dim3(SEQ / 64, NH, BATCH), 128, FA_SMEM>>>(
      qh, kh, kl, vh, aoh);

  // Output projection (single-product fp16)
  gemm_mma_kernel<0><<<dim3(DMODEL / 128, MTOK / 128), 256, GEMM_SMEM>>>(
      aoh, woh, nullptr, out, DMODEL, DMODEL, nullptr, nullptr,
      nullptr, nullptr, nullptr, nullptr);
}